// round 1
// baseline (speedup 1.0000x reference)
#include <cuda_runtime.h>
#include <math.h>

// Gaussian KDE log-likelihood, h = 1.0
//   out[m] = logsumexp_n( cross(m,n) - 0.5*t2[m] - 0.5*r2[n] - Z + log w_n ) ,  w normalized
// Z = 0.5*64*log(2*pi) = 58.812066125099045

#define D   64
#define TM  64
#define TN  64
#define ZCONST 58.812066125099045f

// scratch (device globals: no cudaMalloc allowed)
__device__ float g_t2c[16384];   // -0.5*||test_m||^2 - Z   (only first M used)
__device__ float g_r2h[32768];   // -0.5*||train_n||^2      (only first N used)
__device__ float g_winv;         // 1 / sum(sample_weight)

// ---------------------------------------------------------------------------
// Pre-kernel 1: row norms
// ---------------------------------------------------------------------------
__global__ void kde_pre_rows(const float* __restrict__ testX,
                             const float* __restrict__ trainX,
                             int M, int N) {
    int i = blockIdx.x * blockDim.x + threadIdx.x;
    if (i < M) {
        const float4* p = (const float4*)(testX + (size_t)i * D);
        float s = 0.f;
#pragma unroll
        for (int j = 0; j < D / 4; j++) {
            float4 v = p[j];
            s += v.x * v.x + v.y * v.y + v.z * v.z + v.w * v.w;
        }
        g_t2c[i] = -0.5f * s - ZCONST;
    } else if (i < M + N) {
        int r = i - M;
        const float4* p = (const float4*)(trainX + (size_t)r * D);
        float s = 0.f;
#pragma unroll
        for (int j = 0; j < D / 4; j++) {
            float4 v = p[j];
            s += v.x * v.x + v.y * v.y + v.z * v.z + v.w * v.w;
        }
        g_r2h[r] = -0.5f * s;
    }
}

// ---------------------------------------------------------------------------
// Pre-kernel 2: deterministic weight-sum reduction (single block, fixed tree)
// ---------------------------------------------------------------------------
__global__ void kde_pre_wsum(const float* __restrict__ w, int N) {
    __shared__ float red[256];
    float s = 0.f;
    for (int j = threadIdx.x; j < N; j += 256) s += w[j];
    red[threadIdx.x] = s;
    __syncthreads();
#pragma unroll
    for (int o = 128; o > 0; o >>= 1) {
        if (threadIdx.x < o) red[threadIdx.x] += red[threadIdx.x + o];
        __syncthreads();
    }
    if (threadIdx.x == 0) g_winv = 1.0f / red[0];
}

// ---------------------------------------------------------------------------
// Main kernel: 64x64 block tile, 4x4 thread tile, fused online logsumexp
// ---------------------------------------------------------------------------
__global__ __launch_bounds__(256) void kde_main(
    const float* __restrict__ testX,
    const float* __restrict__ trainX,
    const float* __restrict__ w,
    float* __restrict__ out,
    int N)
{
    __shared__ float sA[D][TM + 1];  // test, [k][m]
    __shared__ float sB[D][TN + 1];  // train, [k][n]
    __shared__ float sR[TN];         // -0.5*r2 tile
    __shared__ float sW[TN];         // raw weights tile

    const int tid = threadIdx.x;
    const int tx  = tid & 15;   // train-col group
    const int ty  = tid >> 4;   // test-row group
    const int m0  = blockIdx.x * TM;

    // load + transpose the test tile (once)
#pragma unroll
    for (int i = 0; i < 4; i++) {
        int idx = tid + i * 256;         // 0..1023
        int r   = idx >> 4;              // tile row 0..63
        int c   = (idx & 15) << 2;       // k group
        float4 v = *(const float4*)(testX + (size_t)(m0 + r) * D + c);
        sA[c + 0][r] = v.x; sA[c + 1][r] = v.y;
        sA[c + 2][r] = v.z; sA[c + 3][r] = v.w;
    }

    float cm[4], vmax[4], vsum[4];
#pragma unroll
    for (int i = 0; i < 4; i++) {
        cm[i]   = g_t2c[m0 + ty * 4 + i];
        vmax[i] = -3.4e38f;
        vsum[i] = 0.f;
    }

    for (int nt = 0; nt < N; nt += TN) {
        __syncthreads();  // previous tile fully consumed (also covers sA on iter 0)
        // load + transpose train tile
#pragma unroll
        for (int i = 0; i < 4; i++) {
            int idx = tid + i * 256;
            int r   = idx >> 4;
            int c   = (idx & 15) << 2;
            float4 v = *(const float4*)(trainX + (size_t)(nt + r) * D + c);
            sB[c + 0][r] = v.x; sB[c + 1][r] = v.y;
            sB[c + 2][r] = v.z; sB[c + 3][r] = v.w;
        }
        if (tid < TN) {
            sR[tid] = g_r2h[nt + tid];
            sW[tid] = w[nt + tid];
        }
        __syncthreads();

        float acc[4][4];
#pragma unroll
        for (int i = 0; i < 4; i++)
#pragma unroll
            for (int j = 0; j < 4; j++) acc[i][j] = 0.f;

#pragma unroll
        for (int k = 0; k < D; k++) {
            float a[4], b[4];
#pragma unroll
            for (int i = 0; i < 4; i++) a[i] = sA[k][ty * 4 + i];
#pragma unroll
            for (int j = 0; j < 4; j++) b[j] = sB[k][tx * 4 + j];
#pragma unroll
            for (int i = 0; i < 4; i++)
#pragma unroll
                for (int j = 0; j < 4; j++)
                    acc[i][j] = fmaf(a[i], b[j], acc[i][j]);
        }

        // fused epilogue: val = cross + cm + rl;  online weighted logsumexp
        float rl[4], wl[4];
#pragma unroll
        for (int j = 0; j < 4; j++) {
            rl[j] = sR[tx * 4 + j];
            wl[j] = sW[tx * 4 + j];
        }
#pragma unroll
        for (int i = 0; i < 4; i++) {
            float v0 = acc[i][0] + cm[i] + rl[0];
            float v1 = acc[i][1] + cm[i] + rl[1];
            float v2 = acc[i][2] + cm[i] + rl[2];
            float v3 = acc[i][3] + cm[i] + rl[3];
            float mx = fmaxf(fmaxf(v0, v1), fmaxf(v2, v3));
            if (mx > vmax[i]) {
                vsum[i] *= __expf(vmax[i] - mx);
                vmax[i]  = mx;
            }
            vsum[i] += __expf(v0 - vmax[i]) * wl[0]
                     + __expf(v1 - vmax[i]) * wl[1]
                     + __expf(v2 - vmax[i]) * wl[2]
                     + __expf(v3 - vmax[i]) * wl[3];
        }
    }

    // combine the 16 tx partials per test row (butterfly within 16-lane groups)
#pragma unroll
    for (int off = 8; off > 0; off >>= 1) {
#pragma unroll
        for (int i = 0; i < 4; i++) {
            float omx = __shfl_xor_sync(0xffffffffu, vmax[i], off);
            float osm = __shfl_xor_sync(0xffffffffu, vsum[i], off);
            float nm  = fmaxf(vmax[i], omx);
            vsum[i] = vsum[i] * __expf(vmax[i] - nm) + osm * __expf(omx - nm);
            vmax[i] = nm;
        }
    }

    if (tx == 0) {
        float winv = g_winv;
#pragma unroll
        for (int i = 0; i < 4; i++)
            out[m0 + ty * 4 + i] = vmax[i] + logf(vsum[i] * winv + 1e-20f);
    }
}

// ---------------------------------------------------------------------------
extern "C" void kernel_launch(void* const* d_in, const int* in_sizes, int n_in,
                              void* d_out, int out_size) {
    const float* testX  = (const float*)d_in[0];
    const float* trainX = (const float*)d_in[1];
    const float* w      = (const float*)d_in[2];
    float* out = (float*)d_out;

    int M = in_sizes[0] / D;   // 8192
    int N = in_sizes[1] / D;   // 16384

    kde_pre_rows<<<(M + N + 255) / 256, 256>>>(testX, trainX, M, N);
    kde_pre_wsum<<<1, 256>>>(w, N);
    kde_main<<<M / TM, 256>>>(testX, trainX, w, out, N);
}

// round 2
// speedup vs baseline: 1.2479x; 1.2479x over previous
#include <cuda_runtime.h>
#include <math.h>

// Gaussian KDE log-likelihood, h = 1.0
//   out[m] = logsumexp_n( cross(m,n) - 0.5*t2[m] - 0.5*r2[n] - Z + log w_n ), w normalized
// Z = 0.5*64*log(2*pi)

#define D   64
#define TM  64
#define TN  64
#define ZCONST 58.812066125099045f

__device__ float g_t2c[16384];   // -0.5*||test_m||^2 - Z
__device__ float g_r2h[32768];   // -0.5*||train_n||^2
__device__ float g_winv;         // 1 / sum(w)

// ---------------- packed f32x2 helpers (FFMA2 path, PTX-only) ----------------
__device__ __forceinline__ unsigned long long pk2(float x, float y) {
    unsigned long long r;
    asm("mov.b64 %0, {%1, %2};" : "=l"(r) : "f"(x), "f"(y));
    return r;
}
__device__ __forceinline__ void fma2(unsigned long long& d,
                                     unsigned long long a, unsigned long long b) {
    asm("fma.rn.f32x2 %0, %1, %2, %0;" : "+l"(d) : "l"(a), "l"(b));
}
__device__ __forceinline__ unsigned long long add2(unsigned long long a,
                                                   unsigned long long b) {
    unsigned long long r;
    asm("add.rn.f32x2 %0, %1, %2;" : "=l"(r) : "l"(a), "l"(b));
    return r;
}
__device__ __forceinline__ float2 upk(unsigned long long v) {
    float2 f;
    asm("mov.b64 {%0, %1}, %2;" : "=f"(f.x), "=f"(f.y) : "l"(v));
    return f;
}

// ---------------------------------------------------------------------------
__global__ void kde_pre_rows(const float* __restrict__ testX,
                             const float* __restrict__ trainX,
                             int M, int N) {
    int i = blockIdx.x * blockDim.x + threadIdx.x;
    if (i < M) {
        const float4* p = (const float4*)(testX + (size_t)i * D);
        float s = 0.f;
#pragma unroll
        for (int j = 0; j < D / 4; j++) {
            float4 v = p[j];
            s += v.x * v.x + v.y * v.y + v.z * v.z + v.w * v.w;
        }
        g_t2c[i] = -0.5f * s - ZCONST;
    } else if (i < M + N) {
        int r = i - M;
        const float4* p = (const float4*)(trainX + (size_t)r * D);
        float s = 0.f;
#pragma unroll
        for (int j = 0; j < D / 4; j++) {
            float4 v = p[j];
            s += v.x * v.x + v.y * v.y + v.z * v.z + v.w * v.w;
        }
        g_r2h[r] = -0.5f * s;
    }
}

__global__ void kde_pre_wsum(const float* __restrict__ w, int N) {
    __shared__ float red[256];
    float s = 0.f;
    for (int j = threadIdx.x; j < N; j += 256) s += w[j];
    red[threadIdx.x] = s;
    __syncthreads();
#pragma unroll
    for (int o = 128; o > 0; o >>= 1) {
        if (threadIdx.x < o) red[threadIdx.x] += red[threadIdx.x + o];
        __syncthreads();
    }
    if (threadIdx.x == 0) g_winv = 1.0f / red[0];
}

// ---------------------------------------------------------------------------
// Main: 64x64 tile, 4x4 thread tile via packed FFMA2, fused online logsumexp.
// Shared layout: transposed [k][r], stride 64 floats (16B-aligned rows),
// XOR swizzle on the 4-row group: word(k,r) = k*64 + (((r>>2) ^ ((k>>2)&15))<<2) + (r&3)
// ---------------------------------------------------------------------------
__global__ __launch_bounds__(256) void kde_main(
    const float* __restrict__ testX,
    const float* __restrict__ trainX,
    const float* __restrict__ w,
    float* __restrict__ out,
    int N)
{
    __shared__ __align__(16) float sA[D * TM];
    __shared__ __align__(16) float sB[D * TN];
    __shared__ __align__(16) float sR[TN];
    __shared__ __align__(16) float sW[TN];

    const int tid = threadIdx.x;
    const int tx  = tid & 15;
    const int ty  = tid >> 4;
    const int m0  = blockIdx.x * TM;

    // per-thread transpose-store slot (r = row, s = k-chunk index)
    const int r_ld = tid >> 4;          // base row for i=0 (adds 16 per i)
    const int s_ld = tid & 15;          // k-chunk (k = 4*s_ld + 0..3)

    // ---- load + transpose test tile into sA (once) ----
#pragma unroll
    for (int i = 0; i < 4; i++) {
        int r = r_ld + i * 16;
        float4 v = *(const float4*)(testX + (size_t)(m0 + r) * D + s_ld * 4);
        int g  = (((r >> 2) ^ s_ld) << 2) + (r & 3);
        sA[(s_ld * 4 + 0) * 64 + g] = v.x;
        sA[(s_ld * 4 + 1) * 64 + g] = v.y;
        sA[(s_ld * 4 + 2) * 64 + g] = v.z;
        sA[(s_ld * 4 + 3) * 64 + g] = v.w;
    }

    float cm[4], vmax[4], vsum[4];
    unsigned long long cm2[4];
#pragma unroll
    for (int i = 0; i < 4; i++) {
        cm[i]   = g_t2c[m0 + ty * 4 + i];
        cm2[i]  = pk2(cm[i], cm[i]);
        vmax[i] = -3.4e38f;
        vsum[i] = 0.f;
    }

    // ---- prefetch first train tile into registers ----
    float4 pv[4];
#pragma unroll
    for (int i = 0; i < 4; i++)
        pv[i] = *(const float4*)(trainX + (size_t)(r_ld + i * 16) * D + s_ld * 4);
    float pr = 0.f, pw = 0.f;
    if (tid < TN) { pr = g_r2h[tid]; pw = w[tid]; }

    for (int nt = 0; nt < N; nt += TN) {
        __syncthreads();   // smem free (prev tile consumed / sA stores pending covered below)
        // store prefetched tile to sB (swizzled transpose)
#pragma unroll
        for (int i = 0; i < 4; i++) {
            int r = r_ld + i * 16;
            int g = (((r >> 2) ^ s_ld) << 2) + (r & 3);
            sB[(s_ld * 4 + 0) * 64 + g] = pv[i].x;
            sB[(s_ld * 4 + 1) * 64 + g] = pv[i].y;
            sB[(s_ld * 4 + 2) * 64 + g] = pv[i].z;
            sB[(s_ld * 4 + 3) * 64 + g] = pv[i].w;
        }
        if (tid < TN) { sR[tid] = pr; sW[tid] = pw; }
        __syncthreads();

        // prefetch next tile (overlaps with compute)
        int nn = nt + TN;
        if (nn < N) {
#pragma unroll
            for (int i = 0; i < 4; i++)
                pv[i] = *(const float4*)(trainX + (size_t)(nn + r_ld + i * 16) * D + s_ld * 4);
            if (tid < TN) { pr = g_r2h[nn + tid]; pw = w[nn + tid]; }
        }

        // ---- GEMM micro-kernel: 8 FFMA2 per k ----
        unsigned long long acc[4][2];
#pragma unroll
        for (int i = 0; i < 4; i++) { acc[i][0] = 0ull; acc[i][1] = 0ull; }

#pragma unroll
        for (int k = 0; k < D; k++) {
            const int sw = (k >> 2) & 15;
            float4 av = *(const float4*)(sA + k * 64 + ((ty ^ sw) << 2));
            float4 bv = *(const float4*)(sB + k * 64 + ((tx ^ sw) << 2));
            unsigned long long b01 = pk2(bv.x, bv.y);
            unsigned long long b23 = pk2(bv.z, bv.w);
            unsigned long long a0 = pk2(av.x, av.x);
            unsigned long long a1 = pk2(av.y, av.y);
            unsigned long long a2 = pk2(av.z, av.z);
            unsigned long long a3 = pk2(av.w, av.w);
            fma2(acc[0][0], a0, b01); fma2(acc[0][1], a0, b23);
            fma2(acc[1][0], a1, b01); fma2(acc[1][1], a1, b23);
            fma2(acc[2][0], a2, b01); fma2(acc[2][1], a2, b23);
            fma2(acc[3][0], a3, b01); fma2(acc[3][1], a3, b23);
        }

        // ---- fused epilogue ----
        float4 rlv = *(const float4*)(sR + tx * 4);
        float4 wlv = *(const float4*)(sW + tx * 4);
        unsigned long long rl01 = pk2(rlv.x, rlv.y);
        unsigned long long rl23 = pk2(rlv.z, rlv.w);
#pragma unroll
        for (int i = 0; i < 4; i++) {
            float2 v01 = upk(add2(add2(acc[i][0], cm2[i]), rl01));
            float2 v23 = upk(add2(add2(acc[i][1], cm2[i]), rl23));
            float mx = fmaxf(fmaxf(v01.x, v01.y), fmaxf(v23.x, v23.y));
            if (mx > vmax[i]) {
                vsum[i] *= __expf(vmax[i] - mx);
                vmax[i]  = mx;
            }
            vsum[i] += __expf(v01.x - vmax[i]) * wlv.x
                     + __expf(v01.y - vmax[i]) * wlv.y
                     + __expf(v23.x - vmax[i]) * wlv.z
                     + __expf(v23.y - vmax[i]) * wlv.w;
        }
    }

    // combine the 16 tx partials per test row
#pragma unroll
    for (int off = 8; off > 0; off >>= 1) {
#pragma unroll
        for (int i = 0; i < 4; i++) {
            float omx = __shfl_xor_sync(0xffffffffu, vmax[i], off);
            float osm = __shfl_xor_sync(0xffffffffu, vsum[i], off);
            float nm  = fmaxf(vmax[i], omx);
            vsum[i] = vsum[i] * __expf(vmax[i] - nm) + osm * __expf(omx - nm);
            vmax[i] = nm;
        }
    }

    if (tx == 0) {
        float winv = g_winv;
#pragma unroll
        for (int i = 0; i < 4; i++)
            out[m0 + ty * 4 + i] = vmax[i] + logf(vsum[i] * winv + 1e-20f);
    }
}

// ---------------------------------------------------------------------------
extern "C" void kernel_launch(void* const* d_in, const int* in_sizes, int n_in,
                              void* d_out, int out_size) {
    const float* testX  = (const float*)d_in[0];
    const float* trainX = (const float*)d_in[1];
    const float* w      = (const float*)d_in[2];
    float* out = (float*)d_out;

    int M = in_sizes[0] / D;   // 8192
    int N = in_sizes[1] / D;   // 16384

    kde_pre_rows<<<(M + N + 255) / 256, 256>>>(testX, trainX, M, N);
    kde_pre_wsum<<<1, 256>>>(w, N);
    kde_main<<<M / TM, 256>>>(testX, trainX, w, out, N);
}

// round 3
// speedup vs baseline: 1.2888x; 1.0328x over previous
#include <cuda_runtime.h>
#include <math.h>

// Gaussian KDE log-likelihood, h = 1.0
// out[m] = logsumexp_n( cross(m,n) - 0.5*t2[m] - 0.5*r2[n] - Z + log w_n ), w normalized

#define D   64
#define TM  64
#define TN  128
#define ZCONST 58.812066125099045f

__device__ float g_t2c[16384];   // -0.5*||test_m||^2 - Z
__device__ float g_r2h[32768];   // -0.5*||train_n||^2
__device__ float g_winv;         // 1 / sum(w)

// ---------------- packed f32x2 helpers ----------------
__device__ __forceinline__ unsigned long long pk2(float x, float y) {
    unsigned long long r;
    asm("mov.b64 %0, {%1, %2};" : "=l"(r) : "f"(x), "f"(y));
    return r;
}
__device__ __forceinline__ void fma2(unsigned long long& d,
                                     unsigned long long a, unsigned long long b) {
    asm("fma.rn.f32x2 %0, %1, %2, %0;" : "+l"(d) : "l"(a), "l"(b));
}
__device__ __forceinline__ unsigned long long add2(unsigned long long a,
                                                   unsigned long long b) {
    unsigned long long r;
    asm("add.rn.f32x2 %0, %1, %2;" : "=l"(r) : "l"(a), "l"(b));
    return r;
}
__device__ __forceinline__ float2 upk(unsigned long long v) {
    float2 f;
    asm("mov.b64 {%0, %1}, %2;" : "=f"(f.x), "=f"(f.y) : "l"(v));
    return f;
}

// ---------------------------------------------------------------------------
__global__ void kde_pre_rows(const float* __restrict__ testX,
                             const float* __restrict__ trainX,
                             int M, int N) {
    int i = blockIdx.x * blockDim.x + threadIdx.x;
    if (i < M) {
        const float4* p = (const float4*)(testX + (size_t)i * D);
        float s = 0.f;
#pragma unroll
        for (int j = 0; j < D / 4; j++) {
            float4 v = p[j];
            s += v.x * v.x + v.y * v.y + v.z * v.z + v.w * v.w;
        }
        g_t2c[i] = -0.5f * s - ZCONST;
    } else if (i < M + N) {
        int r = i - M;
        const float4* p = (const float4*)(trainX + (size_t)r * D);
        float s = 0.f;
#pragma unroll
        for (int j = 0; j < D / 4; j++) {
            float4 v = p[j];
            s += v.x * v.x + v.y * v.y + v.z * v.z + v.w * v.w;
        }
        g_r2h[r] = -0.5f * s;
    }
}

__global__ void kde_pre_wsum(const float* __restrict__ w, int N) {
    __shared__ float red[256];
    float s = 0.f;
    for (int j = threadIdx.x; j < N; j += 256) s += w[j];
    red[threadIdx.x] = s;
    __syncthreads();
#pragma unroll
    for (int o = 128; o > 0; o >>= 1) {
        if (threadIdx.x < o) red[threadIdx.x] += red[threadIdx.x + o];
        __syncthreads();
    }
    if (threadIdx.x == 0) g_winv = 1.0f / red[0];
}

// ---------------------------------------------------------------------------
// Main: block tile 64x128, thread tile 8x4 (rows x cols).
// A-operand LDS is warp-uniform broadcast (ty constant per warp).
// Accumulators packed over col-pairs -> B multiplicand is a natural LDS.128 pair.
// ---------------------------------------------------------------------------
__global__ __launch_bounds__(256) void kde_main(
    const float* __restrict__ testX,
    const float* __restrict__ trainX,
    const float* __restrict__ w,
    float* __restrict__ out,
    int N)
{
    __shared__ __align__(16) float sA[D * TM];   // [k][m], 16KB
    __shared__ __align__(16) float sB[D * TN];   // [k][n], 32KB

    const int tid = threadIdx.x;
    const int tx  = tid & 31;   // col group (4 cols)
    const int ty  = tid >> 5;   // row group (8 rows) == warp id
    const int m0  = blockIdx.x * TM;

    // ---- load + transpose test tile into sA (once) ----
    {
        const int r = tid >> 2;          // 0..63
        const int q = tid & 3;           // k-quarter
#pragma unroll
        for (int qq = 0; qq < 4; qq++) {
            int kb = q * 16 + qq * 4;
            float4 v = *(const float4*)(testX + (size_t)(m0 + r) * D + kb);
            sA[(kb + 0) * TM + r] = v.x;
            sA[(kb + 1) * TM + r] = v.y;
            sA[(kb + 2) * TM + r] = v.z;
            sA[(kb + 3) * TM + r] = v.w;
        }
    }

    // per-row constants and state
    unsigned long long cm2[8];
    float vmax[8], vsum[8];
#pragma unroll
    for (int i = 0; i < 8; i++) {
        float c = g_t2c[m0 + ty * 8 + i];
        cm2[i]  = pk2(c, c);
        vmax[i] = -3.4e38f;
        vsum[i] = 0.f;
    }

    // B tile loading slots: thread covers row r_b = tid>>1, k half = (tid&1)*32
    const int r_b = tid >> 1;
    const int kh  = (tid & 1) * 32;

    // prefetch first B tile
    float4 pv[8];
#pragma unroll
    for (int q = 0; q < 8; q++)
        pv[q] = *(const float4*)(trainX + (size_t)r_b * D + kh + q * 4);

    for (int nt = 0; nt < N; nt += TN) {
        __syncthreads();
        // store prefetched B tile (transpose into [k][n])
#pragma unroll
        for (int q = 0; q < 8; q++) {
            int kb = kh + q * 4;
            sB[(kb + 0) * TN + r_b] = pv[q].x;
            sB[(kb + 1) * TN + r_b] = pv[q].y;
            sB[(kb + 2) * TN + r_b] = pv[q].z;
            sB[(kb + 3) * TN + r_b] = pv[q].w;
        }
        __syncthreads();

        // prefetch next tile
        int nn = nt + TN;
        if (nn < N) {
#pragma unroll
            for (int q = 0; q < 8; q++)
                pv[q] = *(const float4*)(trainX + (size_t)(nn + r_b) * D + kh + q * 4);
        }

        // per-tile column constants (coalesced L2/L1 hits, warp-identical across ty)
        float4 rlv = *(const float4*)(g_r2h + nt + tx * 4);
        float4 wlv = *(const float4*)(w + nt + tx * 4);

        // ---- GEMM micro-kernel: acc[i][p] = {col 2p, col 2p+1} of row i ----
        unsigned long long acc[8][2];
#pragma unroll
        for (int i = 0; i < 8; i++) { acc[i][0] = 0ull; acc[i][1] = 0ull; }

#pragma unroll 16
        for (int k = 0; k < D; k++) {
            // A broadcast: 8 rows
            float4 a0 = *(const float4*)(sA + k * TM + ty * 8);
            float4 a1 = *(const float4*)(sA + k * TM + ty * 8 + 4);
            // B: 4 cols -> 2 natural pairs
            float4 bv = *(const float4*)(sB + k * TN + tx * 4);
            unsigned long long b0 = pk2(bv.x, bv.y);
            unsigned long long b1 = pk2(bv.z, bv.w);
            unsigned long long a2[8];
            a2[0] = pk2(a0.x, a0.x); a2[1] = pk2(a0.y, a0.y);
            a2[2] = pk2(a0.z, a0.z); a2[3] = pk2(a0.w, a0.w);
            a2[4] = pk2(a1.x, a1.x); a2[5] = pk2(a1.y, a1.y);
            a2[6] = pk2(a1.z, a1.z); a2[7] = pk2(a1.w, a1.w);
#pragma unroll
            for (int i = 0; i < 8; i++) {
                fma2(acc[i][0], a2[i], b0);
                fma2(acc[i][1], a2[i], b1);
            }
        }

        // ---- fused epilogue: online weighted logsumexp over 4 cols ----
        unsigned long long rl0 = pk2(rlv.x, rlv.y);
        unsigned long long rl1 = pk2(rlv.z, rlv.w);
#pragma unroll
        for (int i = 0; i < 8; i++) {
            float2 v01 = upk(add2(add2(acc[i][0], cm2[i]), rl0));
            float2 v23 = upk(add2(add2(acc[i][1], cm2[i]), rl1));
            float mx = fmaxf(fmaxf(v01.x, v01.y), fmaxf(v23.x, v23.y));
            if (mx > vmax[i]) {
                vsum[i] *= __expf(vmax[i] - mx);
                vmax[i]  = mx;
            }
            vsum[i] += __expf(v01.x - vmax[i]) * wlv.x
                     + __expf(v01.y - vmax[i]) * wlv.y
                     + __expf(v23.x - vmax[i]) * wlv.z
                     + __expf(v23.y - vmax[i]) * wlv.w;
        }
    }

    // combine 32 tx partials per row (full-warp butterfly; ty constant per warp)
#pragma unroll
    for (int off = 16; off > 0; off >>= 1) {
#pragma unroll
        for (int i = 0; i < 8; i++) {
            float omx = __shfl_xor_sync(0xffffffffu, vmax[i], off);
            float osm = __shfl_xor_sync(0xffffffffu, vsum[i], off);
            float nm  = fmaxf(vmax[i], omx);
            vsum[i] = vsum[i] * __expf(vmax[i] - nm) + osm * __expf(omx - nm);
            vmax[i] = nm;
        }
    }

    if (tx == 0) {
        float winv = g_winv;
#pragma unroll
        for (int i = 0; i < 8; i++)
            out[m0 + ty * 8 + i] = vmax[i] + logf(vsum[i] * winv + 1e-20f);
    }
}

// ---------------------------------------------------------------------------
extern "C" void kernel_launch(void* const* d_in, const int* in_sizes, int n_in,
                              void* d_out, int out_size) {
    const float* testX  = (const float*)d_in[0];
    const float* trainX = (const float*)d_in[1];
    const float* w      = (const float*)d_in[2];
    float* out = (float*)d_out;

    int M = in_sizes[0] / D;   // 8192
    int N = in_sizes[1] / D;   // 16384

    kde_pre_rows<<<(M + N + 255) / 256, 256>>>(testX, trainX, M, N);
    kde_pre_wsum<<<1, 256>>>(w, N);
    kde_main<<<M / TM, 256>>>(testX, trainX, w, out, N);
}

// round 5
// speedup vs baseline: 2.6975x; 2.0931x over previous
#include <cuda_runtime.h>
#include <cuda_bf16.h>
#include <math.h>
#include <stdint.h>

// Gaussian KDE log-likelihood via warp-level bf16 mma.sync (split bf16, 3 passes)
// + fused log2-domain online logsumexp. No 'a'-suffix PTX features.
//
// out[m] = cm_m + ln2*vmax_m + ln(sum_m) - lnW
//   D = (x . y)*log2e   (log2e folded into A)
//   q_j = (ln w_j - 0.5||y_j||^2)*log2e
//   cm_m = -0.5||x_m||^2 - Z

#define D      64
#define ZCONST 58.812066125099045f
#define LOG2E  1.4426950408889634f
#define LN2F   0.6931471805599453f

#define M_ROWS 8192
#define N_ROWS 16384
#define MT     128
#define NT     128
#define NHALF  8192
#define NTILES 64

// ---------------- device scratch ----------------
__device__ __nv_bfloat16 g_Ahi[M_ROWS * D];
__device__ __nv_bfloat16 g_Alo[M_ROWS * D];
__device__ __nv_bfloat16 g_Bhi[N_ROWS * D];
__device__ __nv_bfloat16 g_Blo[N_ROWS * D];
__device__ float g_cm[M_ROWS];
__device__ float g_q2[N_ROWS];
__device__ float g_logW;
__device__ float g_pmax[M_ROWS * 2];
__device__ float g_psum[M_ROWS * 2];

// ---------------- helpers ----------------
__device__ __forceinline__ uint32_t smem_u32(const void* p) {
    uint32_t a;
    asm("{ .reg .u64 t; cvta.to.shared.u64 t, %1; cvt.u32.u64 %0, t; }" : "=r"(a) : "l"(p));
    return a;
}
__device__ __forceinline__ float ex2f(float x) {
    float r; asm("ex2.approx.f32 %0, %1;" : "=f"(r) : "f"(x)); return r;
}
__device__ __forceinline__ void cpa16(uint32_t dst, const void* src) {
    asm volatile("cp.async.cg.shared.global [%0], [%1], 16;" :: "r"(dst), "l"(src));
}
__device__ __forceinline__ void ldsm4(uint32_t& r0, uint32_t& r1, uint32_t& r2,
                                      uint32_t& r3, uint32_t addr) {
    asm volatile("ldmatrix.sync.aligned.m8n8.x4.shared.b16 {%0,%1,%2,%3}, [%4];"
                 : "=r"(r0), "=r"(r1), "=r"(r2), "=r"(r3) : "r"(addr));
}
__device__ __forceinline__ void mma16816(float& c0, float& c1, float& c2, float& c3,
                                         uint32_t a0, uint32_t a1, uint32_t a2, uint32_t a3,
                                         uint32_t b0, uint32_t b1) {
    asm volatile("mma.sync.aligned.m16n8k16.row.col.f32.bf16.bf16.f32 "
                 "{%0,%1,%2,%3}, {%4,%5,%6,%7}, {%8,%9}, {%0,%1,%2,%3};"
                 : "+f"(c0), "+f"(c1), "+f"(c2), "+f"(c3)
                 : "r"(a0), "r"(a1), "r"(a2), "r"(a3), "r"(b0), "r"(b1));
}
#define SWZ(o) ((o) ^ (((o) >> 3) & 0x70))

// ---------------- pre-kernels ----------------
__global__ void kde_pre(const float* __restrict__ testX,
                        const float* __restrict__ trainX,
                        const float* __restrict__ w) {
    int i = blockIdx.x * blockDim.x + threadIdx.x;
    if (i < M_ROWS) {
        const float4* p = (const float4*)(testX + (size_t)i * D);
        float s = 0.f;
#pragma unroll
        for (int j = 0; j < 16; j++) {
            float4 v = p[j];
            s += v.x * v.x + v.y * v.y + v.z * v.z + v.w * v.w;
            float xs[4] = {v.x, v.y, v.z, v.w};
#pragma unroll
            for (int c = 0; c < 4; c++) {
                float x = xs[c] * LOG2E;
                __nv_bfloat16 h = __float2bfloat16(x);
                g_Ahi[(size_t)i * D + j * 4 + c] = h;
                g_Alo[(size_t)i * D + j * 4 + c] = __float2bfloat16(x - __bfloat162float(h));
            }
        }
        g_cm[i] = -0.5f * s - ZCONST;
    } else if (i < M_ROWS + N_ROWS) {
        int r = i - M_ROWS;
        const float4* p = (const float4*)(trainX + (size_t)r * D);
        float s = 0.f;
#pragma unroll
        for (int j = 0; j < 16; j++) {
            float4 v = p[j];
            s += v.x * v.x + v.y * v.y + v.z * v.z + v.w * v.w;
            float xs[4] = {v.x, v.y, v.z, v.w};
#pragma unroll
            for (int c = 0; c < 4; c++) {
                float x = xs[c];
                __nv_bfloat16 h = __float2bfloat16(x);
                g_Bhi[(size_t)r * D + j * 4 + c] = h;
                g_Blo[(size_t)r * D + j * 4 + c] = __float2bfloat16(x - __bfloat162float(h));
            }
        }
        g_q2[r] = (logf(fmaxf(w[r], 1e-37f)) - 0.5f * s) * LOG2E;
    }
}

__global__ void kde_pre_wsum(const float* __restrict__ w, int N) {
    __shared__ float red[256];
    float s = 0.f;
    for (int j = threadIdx.x; j < N; j += 256) s += w[j];
    red[threadIdx.x] = s;
    __syncthreads();
#pragma unroll
    for (int o = 128; o > 0; o >>= 1) {
        if (threadIdx.x < o) red[threadIdx.x] += red[threadIdx.x + o];
        __syncthreads();
    }
    if (threadIdx.x == 0) g_logW = logf(red[0]);
}

// ---------------- main kernel ----------------
// dyn smem: [0, 32KB) q2 half ; [32KB, 96KB) B tiles: buf*32768 + var*16384
#define OB 32768
#define SMEM_BYTES 98304

__global__ __launch_bounds__(256) void kde_main() {
    extern __shared__ char sm[];
    float* sQ = (float*)sm;
    const uint32_t smb = smem_u32(sm);

    const int tid  = threadIdx.x;
    const int wid  = tid >> 5;
    const int lane = tid & 31;
    const int g    = lane >> 2;    // row group 0..7
    const int tc   = lane & 3;     // col-pair in fragment
    const int mtile = blockIdx.x >> 1, half = blockIdx.x & 1;
    const int m0 = mtile * MT;
    const int nbase = half * NHALF;

    // preload q2 half into smem
    {
        const float4* qs = (const float4*)(g_q2 + nbase);
        float4* qd = (float4*)sQ;
        for (int i = tid; i < NHALF / 4; i += 256) qd[i] = qs[i];
    }

    // resident A fragments (rows m0 + wid*16 + {g, g+8}), hi & lo
    uint32_t Ah[4][4], Al[4][4];
    {
        size_t base = (size_t)(m0 + wid * 16 + g) * D + 2 * tc;
#pragma unroll
        for (int ks = 0; ks < 4; ks++) {
            size_t o = base + ks * 16;
            Ah[ks][0] = *(const uint32_t*)(g_Ahi + o);
            Ah[ks][1] = *(const uint32_t*)(g_Ahi + o + 8 * D);
            Ah[ks][2] = *(const uint32_t*)(g_Ahi + o + 8);
            Ah[ks][3] = *(const uint32_t*)(g_Ahi + o + 8 * D + 8);
            Al[ks][0] = *(const uint32_t*)(g_Alo + o);
            Al[ks][1] = *(const uint32_t*)(g_Alo + o + 8 * D);
            Al[ks][2] = *(const uint32_t*)(g_Alo + o + 8);
            Al[ks][3] = *(const uint32_t*)(g_Alo + o + 8 * D + 8);
        }
    }

    // B tile load (cp.async): thread -> variant v, row r, 8 x 16B chunks
    const int vld = tid >> 7;
    const int rld = tid & 127;
    const __nv_bfloat16* gB = vld ? g_Blo : g_Bhi;

    // issue tile 0
    {
        const char* src = (const char*)(gB + (size_t)(nbase + rld) * D);
        uint32_t dst = smb + OB + vld * 16384;
#pragma unroll
        for (int c = 0; c < 8; c++) {
            uint32_t off = rld * 128 + c * 16;
            cpa16(dst + SWZ(off), src + c * 16);
        }
        asm volatile("cp.async.commit_group;" ::: "memory");
    }

    // ldmatrix per-lane base addresses (row-in-matrix = lane&7, matrix id = lane>>3)
    const uint32_t lm_off0 = SWZ((uint32_t)((lane & 7) * 128 + (lane >> 3) * 16));
    const uint32_t lm_off1 = SWZ((uint32_t)((lane & 7) * 128 + 64 + (lane >> 3) * 16));

    float vmax0 = -3.0e38f, vsum0 = 0.f, vmax1 = -3.0e38f, vsum1 = 0.f;

    for (int t = 0; t < NTILES; t++) {
        const int buf = t & 1;
        asm volatile("cp.async.wait_group 0;" ::: "memory");
        __syncthreads();

        // prefetch next tile into other buffer
        if (t + 1 < NTILES) {
            const char* src = (const char*)(gB + (size_t)(nbase + (t + 1) * NT + rld) * D);
            uint32_t dst = smb + OB + (buf ^ 1) * 32768 + vld * 16384;
#pragma unroll
            for (int c = 0; c < 8; c++) {
                uint32_t off = rld * 128 + c * 16;
                cpa16(dst + SWZ(off), src + c * 16);
            }
            asm volatile("cp.async.commit_group;" ::: "memory");
        }

        const uint32_t bhB = smb + OB + buf * 32768;
        const uint32_t blB = bhB + 16384;

        float C[16][4];
#pragma unroll
        for (int ns = 0; ns < 16; ns++) {
            C[ns][0] = 0.f; C[ns][1] = 0.f; C[ns][2] = 0.f; C[ns][3] = 0.f;
        }

#pragma unroll
        for (int ns = 0; ns < 16; ns++) {
            uint32_t bh[8], bl[8];
            ldsm4(bh[0], bh[1], bh[2], bh[3], bhB + ns * 1024 + lm_off0);
            ldsm4(bh[4], bh[5], bh[6], bh[7], bhB + ns * 1024 + lm_off1);
            ldsm4(bl[0], bl[1], bl[2], bl[3], blB + ns * 1024 + lm_off0);
            ldsm4(bl[4], bl[5], bl[6], bl[7], blB + ns * 1024 + lm_off1);
#pragma unroll
            for (int ks = 0; ks < 4; ks++) {
                mma16816(C[ns][0], C[ns][1], C[ns][2], C[ns][3],
                         Ah[ks][0], Ah[ks][1], Ah[ks][2], Ah[ks][3],
                         bh[2 * ks], bh[2 * ks + 1]);
                mma16816(C[ns][0], C[ns][1], C[ns][2], C[ns][3],
                         Ah[ks][0], Ah[ks][1], Ah[ks][2], Ah[ks][3],
                         bl[2 * ks], bl[2 * ks + 1]);
                mma16816(C[ns][0], C[ns][1], C[ns][2], C[ns][3],
                         Al[ks][0], Al[ks][1], Al[ks][2], Al[ks][3],
                         bh[2 * ks], bh[2 * ks + 1]);
            }
        }

        // fused epilogue: add q, online log2-domain LSE for rows g and g+8
        float tmax0 = -3.0e38f, tmax1 = -3.0e38f;
#pragma unroll
        for (int ns = 0; ns < 16; ns++) {
            float2 q = *(const float2*)(sQ + t * NT + ns * 8 + 2 * tc);
            C[ns][0] += q.x; C[ns][1] += q.y;
            C[ns][2] += q.x; C[ns][3] += q.y;
            tmax0 = fmaxf(tmax0, fmaxf(C[ns][0], C[ns][1]));
            tmax1 = fmaxf(tmax1, fmaxf(C[ns][2], C[ns][3]));
        }
        float nm0 = fmaxf(vmax0, tmax0);
        float nm1 = fmaxf(vmax1, tmax1);
        vsum0 *= ex2f(vmax0 - nm0);
        vsum1 *= ex2f(vmax1 - nm1);
        vmax0 = nm0; vmax1 = nm1;
        float s0 = 0.f, s1 = 0.f;
#pragma unroll
        for (int ns = 0; ns < 16; ns++) {
            s0 += ex2f(C[ns][0] - nm0) + ex2f(C[ns][1] - nm0);
            s1 += ex2f(C[ns][2] - nm1) + ex2f(C[ns][3] - nm1);
        }
        vsum0 += s0; vsum1 += s1;

        __syncthreads();   // all warps done reading buf before it is overwritten
    }

    // combine 4 lanes (tc=0..3) holding the same rows
#pragma unroll
    for (int off = 1; off <= 2; off <<= 1) {
        float omx0 = __shfl_xor_sync(0xffffffffu, vmax0, off);
        float osm0 = __shfl_xor_sync(0xffffffffu, vsum0, off);
        float omx1 = __shfl_xor_sync(0xffffffffu, vmax1, off);
        float osm1 = __shfl_xor_sync(0xffffffffu, vsum1, off);
        float nm0 = fmaxf(vmax0, omx0);
        vsum0 = vsum0 * ex2f(vmax0 - nm0) + osm0 * ex2f(omx0 - nm0);
        vmax0 = nm0;
        float nm1 = fmaxf(vmax1, omx1);
        vsum1 = vsum1 * ex2f(vmax1 - nm1) + osm1 * ex2f(omx1 - nm1);
        vmax1 = nm1;
    }

    if (tc == 0) {
        int r0 = m0 + wid * 16 + g;
        g_pmax[(size_t)r0 * 2 + half] = vmax0;
        g_psum[(size_t)r0 * 2 + half] = vsum0;
        g_pmax[(size_t)(r0 + 8) * 2 + half] = vmax1;
        g_psum[(size_t)(r0 + 8) * 2 + half] = vsum1;
    }
}

// ---------------- final combine ----------------
__global__ void kde_final(float* __restrict__ out) {
    int r = blockIdx.x * blockDim.x + threadIdx.x;
    if (r < M_ROWS) {
        float m0 = g_pmax[r * 2 + 0], s0 = g_psum[r * 2 + 0];
        float m1 = g_pmax[r * 2 + 1], s1 = g_psum[r * 2 + 1];
        float m = fmaxf(m0, m1);
        float s = s0 * ex2f(m0 - m) + s1 * ex2f(m1 - m);
        out[r] = g_cm[r] + LN2F * m + logf(s) - g_logW;
    }
}

// ---------------------------------------------------------------------------
extern "C" void kernel_launch(void* const* d_in, const int* in_sizes, int n_in,
                              void* d_out, int out_size) {
    const float* testX  = (const float*)d_in[0];
    const float* trainX = (const float*)d_in[1];
    const float* w      = (const float*)d_in[2];
    float* out = (float*)d_out;

    static int smem_set = 0;
    if (!smem_set) {
        cudaFuncSetAttribute(kde_main, cudaFuncAttributeMaxDynamicSharedMemorySize, SMEM_BYTES);
        smem_set = 1;
    }

    kde_pre<<<(M_ROWS + N_ROWS + 255) / 256, 256>>>(testX, trainX, w);
    kde_pre_wsum<<<1, 256>>>(w, N_ROWS);
    kde_main<<<128, 256, SMEM_BYTES>>>();
    kde_final<<<(M_ROWS + 255) / 256, 256>>>(out);
}

// round 6
// speedup vs baseline: 2.8955x; 1.0734x over previous
#include <cuda_runtime.h>
#include <cuda_bf16.h>
#include <math.h>
#include <stdint.h>

// Gaussian KDE log-likelihood via warp-level bf16 mma.sync (split bf16, 3 passes)
// + fused log2-domain online logsumexp. Baseline PTX only (compute_103-safe).

#define D      64
#define ZCONST 58.812066125099045f
#define LOG2E  1.4426950408889634f
#define LN2F   0.6931471805599453f

#define M_ROWS 8192
#define N_ROWS 16384
#define MT     128
#define NT     128
#define NHALF  8192
#define NTILES 64

// ---------------- device scratch ----------------
__device__ __nv_bfloat16 g_Ahi[M_ROWS * D];
__device__ __nv_bfloat16 g_Alo[M_ROWS * D];
__device__ __nv_bfloat16 g_Bhi[N_ROWS * D];
__device__ __nv_bfloat16 g_Blo[N_ROWS * D];
__device__ float g_cm[M_ROWS];
__device__ float g_q2[N_ROWS];
__device__ float g_logW;
__device__ float g_pmax[M_ROWS * 2];
__device__ float g_psum[M_ROWS * 2];

// ---------------- helpers ----------------
__device__ __forceinline__ uint32_t smem_u32(const void* p) {
    uint32_t a;
    asm("{ .reg .u64 t; cvta.to.shared.u64 t, %1; cvt.u32.u64 %0, t; }" : "=r"(a) : "l"(p));
    return a;
}
__device__ __forceinline__ float ex2f(float x) {
    float r; asm("ex2.approx.f32 %0, %1;" : "=f"(r) : "f"(x)); return r;
}
__device__ __forceinline__ void cpa16(uint32_t dst, const void* src) {
    asm volatile("cp.async.cg.shared.global [%0], [%1], 16;" :: "r"(dst), "l"(src));
}
__device__ __forceinline__ void ldsm4(uint32_t& r0, uint32_t& r1, uint32_t& r2,
                                      uint32_t& r3, uint32_t addr) {
    asm volatile("ldmatrix.sync.aligned.m8n8.x4.shared.b16 {%0,%1,%2,%3}, [%4];"
                 : "=r"(r0), "=r"(r1), "=r"(r2), "=r"(r3) : "r"(addr));
}
__device__ __forceinline__ void mma16816(float* c,
                                         const uint32_t* a,
                                         uint32_t b0, uint32_t b1) {
    asm volatile("mma.sync.aligned.m16n8k16.row.col.f32.bf16.bf16.f32 "
                 "{%0,%1,%2,%3}, {%4,%5,%6,%7}, {%8,%9}, {%0,%1,%2,%3};"
                 : "+f"(c[0]), "+f"(c[1]), "+f"(c[2]), "+f"(c[3])
                 : "r"(a[0]), "r"(a[1]), "r"(a[2]), "r"(a[3]), "r"(b0), "r"(b1));
}
#define SWZ(o) ((o) ^ (((o) >> 3) & 0x70))

// ---------------- pre-kernels ----------------
// 4 threads per row (quarter rows) for MLP; norm via 4-lane shuffle reduce.
__global__ void kde_pre(const float* __restrict__ testX,
                        const float* __restrict__ trainX,
                        const float* __restrict__ w) {
    int gt = blockIdx.x * blockDim.x + threadIdx.x;
    int row = gt >> 2;
    int part = gt & 3;
    bool is_test = row < M_ROWS;
    int r = is_test ? row : row - M_ROWS;
    if (!is_test && r >= N_ROWS) return;

    const float* src = (is_test ? testX : trainX) + (size_t)r * D + part * 16;
    float4 v[4];
    float s = 0.f;
#pragma unroll
    for (int j = 0; j < 4; j++) {
        v[j] = *(const float4*)(src + j * 4);
        s += v[j].x * v[j].x + v[j].y * v[j].y + v[j].z * v[j].z + v[j].w * v[j].w;
    }
    s += __shfl_xor_sync(0xffffffffu, s, 1);
    s += __shfl_xor_sync(0xffffffffu, s, 2);

    const float scale = is_test ? LOG2E : 1.0f;
    __nv_bfloat16* dh = (is_test ? g_Ahi : g_Bhi) + (size_t)r * D + part * 16;
    __nv_bfloat16* dl = (is_test ? g_Alo : g_Blo) + (size_t)r * D + part * 16;
#pragma unroll
    for (int j = 0; j < 4; j++) {
        float xs[4] = {v[j].x, v[j].y, v[j].z, v[j].w};
#pragma unroll
        for (int c = 0; c < 4; c++) {
            float x = xs[c] * scale;
            __nv_bfloat16 h = __float2bfloat16(x);
            dh[j * 4 + c] = h;
            dl[j * 4 + c] = __float2bfloat16(x - __bfloat162float(h));
        }
    }
    if (part == 0) {
        if (is_test) g_cm[r] = -0.5f * s - ZCONST;
        else         g_q2[r] = (logf(fmaxf(w[r], 1e-37f)) - 0.5f * s) * LOG2E;
    }
}

__global__ void kde_pre_wsum(const float* __restrict__ w, int N) {
    __shared__ float red[256];
    float s = 0.f;
    for (int j = threadIdx.x; j < N; j += 256) s += w[j];
    red[threadIdx.x] = s;
    __syncthreads();
#pragma unroll
    for (int o = 128; o > 0; o >>= 1) {
        if (threadIdx.x < o) red[threadIdx.x] += red[threadIdx.x + o];
        __syncthreads();
    }
    if (threadIdx.x == 0) g_logW = logf(red[0]);
}

// ---------------- main kernel ----------------
// dyn smem: [0, 32KB) q2 half ; [32KB, 96KB) B tiles: buf*32768 + var*16384
#define OB 32768
#define SMEM_BYTES 98304

__global__ __launch_bounds__(256) void kde_main() {
    extern __shared__ char sm[];
    float* sQ = (float*)sm;
    const uint32_t smb = smem_u32(sm);

    const int tid  = threadIdx.x;
    const int wid  = tid >> 5;
    const int lane = tid & 31;
    const int g    = lane >> 2;
    const int tc   = lane & 3;
    const int mtile = blockIdx.x >> 1, half = blockIdx.x & 1;
    const int m0 = mtile * MT;
    const int nbase = half * NHALF;

    // preload q2 half into smem
    {
        const float4* qs = (const float4*)(g_q2 + nbase);
        float4* qd = (float4*)sQ;
        for (int i = tid; i < NHALF / 4; i += 256) qd[i] = qs[i];
    }

    // resident A fragments (rows m0 + wid*16 + {g, g+8}), hi & lo
    uint32_t Ah[4][4], Al[4][4];
    {
        size_t base = (size_t)(m0 + wid * 16 + g) * D + 2 * tc;
#pragma unroll
        for (int ks = 0; ks < 4; ks++) {
            size_t o = base + ks * 16;
            Ah[ks][0] = *(const uint32_t*)(g_Ahi + o);
            Ah[ks][1] = *(const uint32_t*)(g_Ahi + o + 8 * D);
            Ah[ks][2] = *(const uint32_t*)(g_Ahi + o + 8);
            Ah[ks][3] = *(const uint32_t*)(g_Ahi + o + 8 * D + 8);
            Al[ks][0] = *(const uint32_t*)(g_Alo + o);
            Al[ks][1] = *(const uint32_t*)(g_Alo + o + 8 * D);
            Al[ks][2] = *(const uint32_t*)(g_Alo + o + 8);
            Al[ks][3] = *(const uint32_t*)(g_Alo + o + 8 * D + 8);
        }
    }

    // B tile loader: thread -> variant v (hi/lo), row r, 8 x 16B chunks
    const int vld = tid >> 7;
    const int rld = tid & 127;
    const __nv_bfloat16* gB = vld ? g_Blo : g_Bhi;

    // issue tile 0
    {
        const char* src = (const char*)(gB + (size_t)(nbase + rld) * D);
        uint32_t dst = smb + OB + vld * 16384;
#pragma unroll
        for (int c = 0; c < 8; c++) {
            uint32_t off = rld * 128 + c * 16;
            cpa16(dst + SWZ(off), src + c * 16);
        }
        asm volatile("cp.async.commit_group;" ::: "memory");
    }

    const uint32_t lm_off0 = SWZ((uint32_t)((lane & 7) * 128 + (lane >> 3) * 16));
    const uint32_t lm_off1 = SWZ((uint32_t)((lane & 7) * 128 + 64 + (lane >> 3) * 16));

    float vmax0 = -3.0e38f, vsum0 = 0.f, vmax1 = -3.0e38f, vsum1 = 0.f;

    for (int t = 0; t < NTILES; t++) {
        const int buf = t & 1;
        asm volatile("cp.async.wait_group 0;" ::: "memory");
        __syncthreads();

        // prefetch next tile into other buffer
        if (t + 1 < NTILES) {
            const char* src = (const char*)(gB + (size_t)(nbase + (t + 1) * NT + rld) * D);
            uint32_t dst = smb + OB + (buf ^ 1) * 32768 + vld * 16384;
#pragma unroll
            for (int c = 0; c < 8; c++) {
                uint32_t off = rld * 128 + c * 16;
                cpa16(dst + SWZ(off), src + c * 16);
            }
            asm volatile("cp.async.commit_group;" ::: "memory");
        }

        const uint32_t bhB = smb + OB + buf * 32768;
        const uint32_t blB = bhB + 16384;

        float C[16][4];
#pragma unroll
        for (int ns = 0; ns < 16; ns++) {
            C[ns][0] = 0.f; C[ns][1] = 0.f; C[ns][2] = 0.f; C[ns][3] = 0.f;
        }

        // groups of 4 ns: 4 independent accumulator chains -> pipelined HMMA issue
#pragma unroll
        for (int ng = 0; ng < 4; ng++) {
            uint32_t bh[4][8], bl[4][8];
#pragma unroll
            for (int j = 0; j < 4; j++) {
                uint32_t nb = (ng * 4 + j) * 1024;
                ldsm4(bh[j][0], bh[j][1], bh[j][2], bh[j][3], bhB + nb + lm_off0);
                ldsm4(bh[j][4], bh[j][5], bh[j][6], bh[j][7], bhB + nb + lm_off1);
                ldsm4(bl[j][0], bl[j][1], bl[j][2], bl[j][3], blB + nb + lm_off0);
                ldsm4(bl[j][4], bl[j][5], bl[j][6], bl[j][7], blB + nb + lm_off1);
            }
#pragma unroll
            for (int ks = 0; ks < 4; ks++) {
#pragma unroll
                for (int j = 0; j < 4; j++)
                    mma16816(C[ng * 4 + j], Ah[ks], bh[j][2 * ks], bh[j][2 * ks + 1]);
#pragma unroll
                for (int j = 0; j < 4; j++)
                    mma16816(C[ng * 4 + j], Ah[ks], bl[j][2 * ks], bl[j][2 * ks + 1]);
#pragma unroll
                for (int j = 0; j < 4; j++)
                    mma16816(C[ng * 4 + j], Al[ks], bh[j][2 * ks], bh[j][2 * ks + 1]);
            }
        }

        // fused epilogue: add q, tree max, online log2-domain LSE
#pragma unroll
        for (int ns = 0; ns < 16; ns++) {
            float2 q = *(const float2*)(sQ + t * NT + ns * 8 + 2 * tc);
            C[ns][0] += q.x; C[ns][1] += q.y;
            C[ns][2] += q.x; C[ns][3] += q.y;
        }
        float m0a[8], m1a[8];
#pragma unroll
        for (int i = 0; i < 8; i++) {
            m0a[i] = fmaxf(fmaxf(C[2 * i][0], C[2 * i][1]),
                           fmaxf(C[2 * i + 1][0], C[2 * i + 1][1]));
            m1a[i] = fmaxf(fmaxf(C[2 * i][2], C[2 * i][3]),
                           fmaxf(C[2 * i + 1][2], C[2 * i + 1][3]));
        }
#pragma unroll
        for (int o = 4; o > 0; o >>= 1)
#pragma unroll
            for (int i = 0; i < o; i++) {
                m0a[i] = fmaxf(m0a[i], m0a[i + o]);
                m1a[i] = fmaxf(m1a[i], m1a[i + o]);
            }
        float nm0 = fmaxf(vmax0, m0a[0]);
        float nm1 = fmaxf(vmax1, m1a[0]);
        vsum0 *= ex2f(vmax0 - nm0);
        vsum1 *= ex2f(vmax1 - nm1);
        vmax0 = nm0; vmax1 = nm1;
        float s0a = 0.f, s0b = 0.f, s1a = 0.f, s1b = 0.f;
#pragma unroll
        for (int ns = 0; ns < 16; ns += 2) {
            s0a += ex2f(C[ns][0] - nm0) + ex2f(C[ns][1] - nm0);
            s0b += ex2f(C[ns + 1][0] - nm0) + ex2f(C[ns + 1][1] - nm0);
            s1a += ex2f(C[ns][2] - nm1) + ex2f(C[ns][3] - nm1);
            s1b += ex2f(C[ns + 1][2] - nm1) + ex2f(C[ns + 1][3] - nm1);
        }
        vsum0 += s0a + s0b;
        vsum1 += s1a + s1b;

        __syncthreads();
    }

    // combine 4 lanes (tc = 0..3) holding the same rows
#pragma unroll
    for (int off = 1; off <= 2; off <<= 1) {
        float omx0 = __shfl_xor_sync(0xffffffffu, vmax0, off);
        float osm0 = __shfl_xor_sync(0xffffffffu, vsum0, off);
        float omx1 = __shfl_xor_sync(0xffffffffu, vmax1, off);
        float osm1 = __shfl_xor_sync(0xffffffffu, vsum1, off);
        float nm0 = fmaxf(vmax0, omx0);
        vsum0 = vsum0 * ex2f(vmax0 - nm0) + osm0 * ex2f(omx0 - nm0);
        vmax0 = nm0;
        float nm1 = fmaxf(vmax1, omx1);
        vsum1 = vsum1 * ex2f(vmax1 - nm1) + osm1 * ex2f(omx1 - nm1);
        vmax1 = nm1;
    }

    if (tc == 0) {
        int r0 = m0 + wid * 16 + g;
        g_pmax[(size_t)r0 * 2 + half] = vmax0;
        g_psum[(size_t)r0 * 2 + half] = vsum0;
        g_pmax[(size_t)(r0 + 8) * 2 + half] = vmax1;
        g_psum[(size_t)(r0 + 8) * 2 + half] = vsum1;
    }
}

// ---------------- final combine ----------------
__global__ void kde_final(float* __restrict__ out) {
    int r = blockIdx.x * blockDim.x + threadIdx.x;
    if (r < M_ROWS) {
        float m0 = g_pmax[r * 2 + 0], s0 = g_psum[r * 2 + 0];
        float m1 = g_pmax[r * 2 + 1], s1 = g_psum[r * 2 + 1];
        float m = fmaxf(m0, m1);
        float s = s0 * ex2f(m0 - m) + s1 * ex2f(m1 - m);
        out[r] = g_cm[r] + LN2F * m + logf(s) - g_logW;
    }
}

// ---------------------------------------------------------------------------
extern "C" void kernel_launch(void* const* d_in, const int* in_sizes, int n_in,
                              void* d_out, int out_size) {
    const float* testX  = (const float*)d_in[0];
    const float* trainX = (const float*)d_in[1];
    const float* w      = (const float*)d_in[2];
    float* out = (float*)d_out;

    static int smem_set = 0;
    if (!smem_set) {
        cudaFuncSetAttribute(kde_main, cudaFuncAttributeMaxDynamicSharedMemorySize, SMEM_BYTES);
        smem_set = 1;
    }

    kde_pre<<<((M_ROWS + N_ROWS) * 4 + 255) / 256, 256>>>(testX, trainX, w);
    kde_pre_wsum<<<1, 256>>>(w, N_ROWS);
    kde_main<<<128, 256, SMEM_BYTES>>>();
    kde_final<<<(M_ROWS + 255) / 256, 256>>>(out);
}

// round 7
// speedup vs baseline: 5.4647x; 1.8873x over previous
#include <cuda_runtime.h>
#include <cuda_fp16.h>
#include <math.h>
#include <stdint.h>

// Gaussian KDE log-likelihood via warp-level fp16 mma.sync (single pass, exact
// fp16 products in fp32 accum) + fused log2-domain online logsumexp with
// tile-skip. Baseline PTX only (compute_103-safe).

#define D      64
#define ZCONST 58.812066125099045f
#define LOG2E  1.4426950408889634f
#define LN2F   0.6931471805599453f

#define M_ROWS 8192
#define N_ROWS 16384
#define MT     128
#define NT     128
#define NHALF  8192
#define NTILES 64
#define SKIP_THRESH 32.0f

// ---------------- device scratch ----------------
__device__ __half g_A16[M_ROWS * D];   // test * log2e
__device__ __half g_B16[N_ROWS * D];   // train
__device__ float g_cm[M_ROWS];
__device__ float g_q2[N_ROWS];
__device__ float g_logW;
__device__ float g_pmax[M_ROWS * 2];
__device__ float g_psum[M_ROWS * 2];

// ---------------- helpers ----------------
__device__ __forceinline__ uint32_t smem_u32(const void* p) {
    uint32_t a;
    asm("{ .reg .u64 t; cvta.to.shared.u64 t, %1; cvt.u32.u64 %0, t; }" : "=r"(a) : "l"(p));
    return a;
}
__device__ __forceinline__ float ex2f(float x) {
    float r; asm("ex2.approx.f32 %0, %1;" : "=f"(r) : "f"(x)); return r;
}
__device__ __forceinline__ void cpa16(uint32_t dst, const void* src) {
    asm volatile("cp.async.cg.shared.global [%0], [%1], 16;" :: "r"(dst), "l"(src));
}
__device__ __forceinline__ void ldsm4(uint32_t& r0, uint32_t& r1, uint32_t& r2,
                                      uint32_t& r3, uint32_t addr) {
    asm volatile("ldmatrix.sync.aligned.m8n8.x4.shared.b16 {%0,%1,%2,%3}, [%4];"
                 : "=r"(r0), "=r"(r1), "=r"(r2), "=r"(r3) : "r"(addr));
}
__device__ __forceinline__ void mma16816(float* c, const uint32_t* a,
                                         uint32_t b0, uint32_t b1) {
    asm volatile("mma.sync.aligned.m16n8k16.row.col.f32.f16.f16.f32 "
                 "{%0,%1,%2,%3}, {%4,%5,%6,%7}, {%8,%9}, {%0,%1,%2,%3};"
                 : "+f"(c[0]), "+f"(c[1]), "+f"(c[2]), "+f"(c[3])
                 : "r"(a[0]), "r"(a[1]), "r"(a[2]), "r"(a[3]), "r"(b0), "r"(b1));
}
#define SWZ(o) ((o) ^ (((o) >> 3) & 0x70))

// ---------------- pre-kernels ----------------
__global__ void kde_pre(const float* __restrict__ testX,
                        const float* __restrict__ trainX,
                        const float* __restrict__ w) {
    int gt = blockIdx.x * blockDim.x + threadIdx.x;
    int row = gt >> 2;
    int part = gt & 3;
    bool is_test = row < M_ROWS;
    int r = is_test ? row : row - M_ROWS;
    if (!is_test && r >= N_ROWS) return;

    const float* src = (is_test ? testX : trainX) + (size_t)r * D + part * 16;
    float4 v[4];
    float s = 0.f;
#pragma unroll
    for (int j = 0; j < 4; j++) {
        v[j] = *(const float4*)(src + j * 4);
        s += v[j].x * v[j].x + v[j].y * v[j].y + v[j].z * v[j].z + v[j].w * v[j].w;
    }
    s += __shfl_xor_sync(0xffffffffu, s, 1);
    s += __shfl_xor_sync(0xffffffffu, s, 2);

    const float scale = is_test ? LOG2E : 1.0f;
    __half* dst = (is_test ? g_A16 : g_B16) + (size_t)r * D + part * 16;
#pragma unroll
    for (int j = 0; j < 4; j++) {
        float xs[4] = {v[j].x, v[j].y, v[j].z, v[j].w};
#pragma unroll
        for (int c = 0; c < 4; c++)
            dst[j * 4 + c] = __float2half_rn(xs[c] * scale);
    }
    if (part == 0) {
        if (is_test) g_cm[r] = -0.5f * s - ZCONST;
        else         g_q2[r] = (logf(fmaxf(w[r], 1e-37f)) - 0.5f * s) * LOG2E;
    }
}

__global__ void kde_pre_wsum(const float* __restrict__ w, int N) {
    __shared__ float red[256];
    float s = 0.f;
    for (int j = threadIdx.x; j < N; j += 256) s += w[j];
    red[threadIdx.x] = s;
    __syncthreads();
#pragma unroll
    for (int o = 128; o > 0; o >>= 1) {
        if (threadIdx.x < o) red[threadIdx.x] += red[threadIdx.x + o];
        __syncthreads();
    }
    if (threadIdx.x == 0) g_logW = logf(red[0]);
}

// ---------------- main kernel ----------------
// dyn smem: [0, 32KB) q2 half ; [32KB, 64KB) B tiles: buf*16384
#define OB 32768
#define SMEM_BYTES 65536

__global__ __launch_bounds__(256) void kde_main() {
    extern __shared__ char sm[];
    float* sQ = (float*)sm;
    const uint32_t smb = smem_u32(sm);

    const int tid  = threadIdx.x;
    const int wid  = tid >> 5;
    const int lane = tid & 31;
    const int g    = lane >> 2;
    const int tc   = lane & 3;
    const int mtile = blockIdx.x >> 1, half = blockIdx.x & 1;
    const int m0 = mtile * MT;
    const int nbase = half * NHALF;

    // preload q2 half into smem
    {
        const float4* qs = (const float4*)(g_q2 + nbase);
        float4* qd = (float4*)sQ;
        for (int i = tid; i < NHALF / 4; i += 256) qd[i] = qs[i];
    }

    // resident A fragments (rows m0 + wid*16 + {g, g+8})
    uint32_t A[4][4];
    {
        size_t base = (size_t)(m0 + wid * 16 + g) * D + 2 * tc;
#pragma unroll
        for (int ks = 0; ks < 4; ks++) {
            size_t o = base + ks * 16;
            A[ks][0] = *(const uint32_t*)(g_A16 + o);
            A[ks][1] = *(const uint32_t*)(g_A16 + o + 8 * D);
            A[ks][2] = *(const uint32_t*)(g_A16 + o + 8);
            A[ks][3] = *(const uint32_t*)(g_A16 + o + 8 * D + 8);
        }
    }

    // B tile loader: 2 threads per row, 4 x 16B chunks each
    const int rld = tid >> 1;
    const int cb  = (tid & 1) * 4;

    // issue tile 0
    {
        const char* src = (const char*)(g_B16 + (size_t)(nbase + rld) * D) + cb * 16;
        uint32_t dst = smb + OB;
#pragma unroll
        for (int c = 0; c < 4; c++) {
            uint32_t off = rld * 128 + (cb + c) * 16;
            cpa16(dst + SWZ(off), src + c * 16);
        }
        asm volatile("cp.async.commit_group;" ::: "memory");
    }

    const uint32_t lm_off0 = SWZ((uint32_t)((lane & 7) * 128 + (lane >> 3) * 16));
    const uint32_t lm_off1 = SWZ((uint32_t)((lane & 7) * 128 + 64 + (lane >> 3) * 16));

    float vmax0 = -3.0e38f, vsum0 = 0.f, vmax1 = -3.0e38f, vsum1 = 0.f;

    for (int t = 0; t < NTILES; t++) {
        const int buf = t & 1;
        asm volatile("cp.async.wait_group 0;" ::: "memory");
        __syncthreads();

        // prefetch next tile into other buffer
        if (t + 1 < NTILES) {
            const char* src = (const char*)(g_B16 + (size_t)(nbase + (t + 1) * NT + rld) * D) + cb * 16;
            uint32_t dst = smb + OB + (buf ^ 1) * 16384;
#pragma unroll
            for (int c = 0; c < 4; c++) {
                uint32_t off = rld * 128 + (cb + c) * 16;
                cpa16(dst + SWZ(off), src + c * 16);
            }
            asm volatile("cp.async.commit_group;" ::: "memory");
        }

        const uint32_t bB = smb + OB + buf * 16384;

        float C[16][4];
#pragma unroll
        for (int ns = 0; ns < 16; ns++) {
            C[ns][0] = 0.f; C[ns][1] = 0.f; C[ns][2] = 0.f; C[ns][3] = 0.f;
        }

        // 4 ns-groups of 4: independent accumulator chains
#pragma unroll
        for (int ng = 0; ng < 4; ng++) {
            uint32_t b[4][8];
#pragma unroll
            for (int j = 0; j < 4; j++) {
                uint32_t nb = (ng * 4 + j) * 1024;
                ldsm4(b[j][0], b[j][1], b[j][2], b[j][3], bB + nb + lm_off0);
                ldsm4(b[j][4], b[j][5], b[j][6], b[j][7], bB + nb + lm_off1);
            }
#pragma unroll
            for (int ks = 0; ks < 4; ks++)
#pragma unroll
                for (int j = 0; j < 4; j++)
                    mma16816(C[ng * 4 + j], A[ks], b[j][2 * ks], b[j][2 * ks + 1]);
        }

        // fused epilogue: add q, tree max, tile-skip, online log2 LSE
#pragma unroll
        for (int ns = 0; ns < 16; ns++) {
            float2 q = *(const float2*)(sQ + t * NT + ns * 8 + 2 * tc);
            C[ns][0] += q.x; C[ns][1] += q.y;
            C[ns][2] += q.x; C[ns][3] += q.y;
        }
        float m0a[8], m1a[8];
#pragma unroll
        for (int i = 0; i < 8; i++) {
            m0a[i] = fmaxf(fmaxf(C[2 * i][0], C[2 * i][1]),
                           fmaxf(C[2 * i + 1][0], C[2 * i + 1][1]));
            m1a[i] = fmaxf(fmaxf(C[2 * i][2], C[2 * i][3]),
                           fmaxf(C[2 * i + 1][2], C[2 * i + 1][3]));
        }
#pragma unroll
        for (int o = 4; o > 0; o >>= 1)
#pragma unroll
            for (int i = 0; i < o; i++) {
                m0a[i] = fmaxf(m0a[i], m0a[i + o]);
                m1a[i] = fmaxf(m1a[i], m1a[i + o]);
            }

        bool skip = (m0a[0] < vmax0 - SKIP_THRESH) && (m1a[0] < vmax1 - SKIP_THRESH);
        if (!__all_sync(0xffffffffu, skip)) {
            float nm0 = fmaxf(vmax0, m0a[0]);
            float nm1 = fmaxf(vmax1, m1a[0]);
            vsum0 *= ex2f(vmax0 - nm0);
            vsum1 *= ex2f(vmax1 - nm1);
            vmax0 = nm0; vmax1 = nm1;
            float s0a = 0.f, s0b = 0.f, s1a = 0.f, s1b = 0.f;
#pragma unroll
            for (int ns = 0; ns < 16; ns += 2) {
                s0a += ex2f(C[ns][0] - nm0) + ex2f(C[ns][1] - nm0);
                s0b += ex2f(C[ns + 1][0] - nm0) + ex2f(C[ns + 1][1] - nm0);
                s1a += ex2f(C[ns][2] - nm1) + ex2f(C[ns][3] - nm1);
                s1b += ex2f(C[ns + 1][2] - nm1) + ex2f(C[ns + 1][3] - nm1);
            }
            vsum0 += s0a + s0b;
            vsum1 += s1a + s1b;
        }

        __syncthreads();
    }

    // combine 4 lanes (tc = 0..3) holding the same rows
#pragma unroll
    for (int off = 1; off <= 2; off <<= 1) {
        float omx0 = __shfl_xor_sync(0xffffffffu, vmax0, off);
        float osm0 = __shfl_xor_sync(0xffffffffu, vsum0, off);
        float omx1 = __shfl_xor_sync(0xffffffffu, vmax1, off);
        float osm1 = __shfl_xor_sync(0xffffffffu, vsum1, off);
        float nm0 = fmaxf(vmax0, omx0);
        vsum0 = vsum0 * ex2f(vmax0 - nm0) + osm0 * ex2f(omx0 - nm0);
        vmax0 = nm0;
        float nm1 = fmaxf(vmax1, omx1);
        vsum1 = vsum1 * ex2f(vmax1 - nm1) + osm1 * ex2f(omx1 - nm1);
        vmax1 = nm1;
    }

    if (tc == 0) {
        int r0 = m0 + wid * 16 + g;
        g_pmax[(size_t)r0 * 2 + half] = vmax0;
        g_psum[(size_t)r0 * 2 + half] = vsum0;
        g_pmax[(size_t)(r0 + 8) * 2 + half] = vmax1;
        g_psum[(size_t)(r0 + 8) * 2 + half] = vsum1;
    }
}

// ---------------- final combine ----------------
__global__ void kde_final(float* __restrict__ out) {
    int r = blockIdx.x * blockDim.x + threadIdx.x;
    if (r < M_ROWS) {
        float m0 = g_pmax[r * 2 + 0], s0 = g_psum[r * 2 + 0];
        float m1 = g_pmax[r * 2 + 1], s1 = g_psum[r * 2 + 1];
        float m = fmaxf(m0, m1);
        float s = s0 * ex2f(m0 - m) + s1 * ex2f(m1 - m);
        out[r] = g_cm[r] + LN2F * m + logf(s) - g_logW;
    }
}

// ---------------------------------------------------------------------------
extern "C" void kernel_launch(void* const* d_in, const int* in_sizes, int n_in,
                              void* d_out, int out_size) {
    const float* testX  = (const float*)d_in[0];
    const float* trainX = (const float*)d_in[1];
    const float* w      = (const float*)d_in[2];
    float* out = (float*)d_out;

    static int smem_set = 0;
    if (!smem_set) {
        cudaFuncSetAttribute(kde_main, cudaFuncAttributeMaxDynamicSharedMemorySize, SMEM_BYTES);
        smem_set = 1;
    }

    kde_pre<<<((M_ROWS + N_ROWS) * 4 + 255) / 256, 256>>>(testX, trainX, w);
    kde_pre_wsum<<<1, 256>>>(w, N_ROWS);
    kde_main<<<128, 256, SMEM_BYTES>>>();
    kde_final<<<(M_ROWS + 255) / 256, 256>>>(out);
}

// round 8
// speedup vs baseline: 6.2345x; 1.1409x over previous
#include <cuda_runtime.h>
#include <cuda_fp16.h>
#include <math.h>
#include <stdint.h>

// Gaussian KDE log-likelihood via warp-level fp16 mma.sync + fused log2-domain
// logsumexp with constant-reference-max epilogue interleaved into the MMA
// stream. Baseline PTX only (compute_103-safe).

#define D      64
#define ZCONST 58.812066125099045f
#define LOG2E  1.4426950408889634f
#define LN2F   0.6931471805599453f

#define M_ROWS 8192
#define N_ROWS 16384
#define MT     128
#define NT     128
#define NHALF  8192
#define NTILES 64

// ---------------- device scratch ----------------
__device__ __half g_A16[M_ROWS * D];   // test * log2e
__device__ __half g_B16[N_ROWS * D];   // train
__device__ float g_cm[M_ROWS];
__device__ float g_q2[N_ROWS];
__device__ float g_logW;
__device__ float g_pmax[M_ROWS * 2];
__device__ float g_psum[M_ROWS * 2];

// ---------------- helpers ----------------
__device__ __forceinline__ uint32_t smem_u32(const void* p) {
    uint32_t a;
    asm("{ .reg .u64 t; cvta.to.shared.u64 t, %1; cvt.u32.u64 %0, t; }" : "=r"(a) : "l"(p));
    return a;
}
__device__ __forceinline__ float ex2f(float x) {
    float r; asm("ex2.approx.f32 %0, %1;" : "=f"(r) : "f"(x)); return r;
}
__device__ __forceinline__ void cpa16(uint32_t dst, const void* src) {
    asm volatile("cp.async.cg.shared.global [%0], [%1], 16;" :: "r"(dst), "l"(src));
}
__device__ __forceinline__ void ldsm4(uint32_t& r0, uint32_t& r1, uint32_t& r2,
                                      uint32_t& r3, uint32_t addr) {
    asm volatile("ldmatrix.sync.aligned.m8n8.x4.shared.b16 {%0,%1,%2,%3}, [%4];"
                 : "=r"(r0), "=r"(r1), "=r"(r2), "=r"(r3) : "r"(addr));
}
__device__ __forceinline__ void mma16816(float* c, const uint32_t* a,
                                         uint32_t b0, uint32_t b1) {
    asm volatile("mma.sync.aligned.m16n8k16.row.col.f32.f16.f16.f32 "
                 "{%0,%1,%2,%3}, {%4,%5,%6,%7}, {%8,%9}, {%0,%1,%2,%3};"
                 : "+f"(c[0]), "+f"(c[1]), "+f"(c[2]), "+f"(c[3])
                 : "r"(a[0]), "r"(a[1]), "r"(a[2]), "r"(a[3]), "r"(b0), "r"(b1));
}
#define SWZ(o) ((o) ^ (((o) >> 3) & 0x70))

// ---------------- pre-kernels ----------------
__global__ void kde_pre(const float* __restrict__ testX,
                        const float* __restrict__ trainX,
                        const float* __restrict__ w) {
    int gt = blockIdx.x * blockDim.x + threadIdx.x;
    int row = gt >> 2;
    int part = gt & 3;
    bool is_test = row < M_ROWS;
    int r = is_test ? row : row - M_ROWS;
    if (!is_test && r >= N_ROWS) return;

    const float* src = (is_test ? testX : trainX) + (size_t)r * D + part * 16;
    float4 v[4];
    float s = 0.f;
#pragma unroll
    for (int j = 0; j < 4; j++) {
        v[j] = *(const float4*)(src + j * 4);
        s += v[j].x * v[j].x + v[j].y * v[j].y + v[j].z * v[j].z + v[j].w * v[j].w;
    }
    s += __shfl_xor_sync(0xffffffffu, s, 1);
    s += __shfl_xor_sync(0xffffffffu, s, 2);

    const float scale = is_test ? LOG2E : 1.0f;
    __half* dst = (is_test ? g_A16 : g_B16) + (size_t)r * D + part * 16;
#pragma unroll
    for (int j = 0; j < 4; j++) {
        float xs[4] = {v[j].x, v[j].y, v[j].z, v[j].w};
#pragma unroll
        for (int c = 0; c < 4; c++)
            dst[j * 4 + c] = __float2half_rn(xs[c] * scale);
    }
    if (part == 0) {
        if (is_test) g_cm[r] = -0.5f * s - ZCONST;
        else         g_q2[r] = (logf(fmaxf(w[r], 1e-37f)) - 0.5f * s) * LOG2E;
    }
}

__global__ void kde_pre_wsum(const float* __restrict__ w, int N) {
    __shared__ float red[256];
    float s = 0.f;
    for (int j = threadIdx.x; j < N; j += 256) s += w[j];
    red[threadIdx.x] = s;
    __syncthreads();
#pragma unroll
    for (int o = 128; o > 0; o >>= 1) {
        if (threadIdx.x < o) red[threadIdx.x] += red[threadIdx.x + o];
        __syncthreads();
    }
    if (threadIdx.x == 0) g_logW = logf(red[0]);
}

// ---------------- main kernel ----------------
// dyn smem: [0, 32KB) q2 half ; [32KB, 64KB) B tiles: buf*16384
#define OB 32768
#define SMEM_BYTES 65536

__global__ __launch_bounds__(256, 1) void kde_main() {
    extern __shared__ char sm[];
    float* sQ = (float*)sm;
    const uint32_t smb = smem_u32(sm);

    const int tid  = threadIdx.x;
    const int wid  = tid >> 5;
    const int lane = tid & 31;
    const int g    = lane >> 2;
    const int tc   = lane & 3;
    const int mtile = blockIdx.x >> 1, half = blockIdx.x & 1;
    const int m0 = mtile * MT;
    const int nbase = half * NHALF;

    // preload q2 half into smem
    {
        const float4* qs = (const float4*)(g_q2 + nbase);
        float4* qd = (float4*)sQ;
        for (int i = tid; i < NHALF / 4; i += 256) qd[i] = qs[i];
    }

    // resident A fragments (rows m0 + wid*16 + {g, g+8})
    uint32_t A[4][4];
    {
        size_t base = (size_t)(m0 + wid * 16 + g) * D + 2 * tc;
#pragma unroll
        for (int ks = 0; ks < 4; ks++) {
            size_t o = base + ks * 16;
            A[ks][0] = *(const uint32_t*)(g_A16 + o);
            A[ks][1] = *(const uint32_t*)(g_A16 + o + 8 * D);
            A[ks][2] = *(const uint32_t*)(g_A16 + o + 8);
            A[ks][3] = *(const uint32_t*)(g_A16 + o + 8 * D + 8);
        }
    }

    // B tile loader: 2 threads per row, 4 x 16B chunks each
    const int rld = tid >> 1;
    const int cb  = (tid & 1) * 4;

    // issue tile 0
    {
        const char* src = (const char*)(g_B16 + (size_t)(nbase + rld) * D) + cb * 16;
        uint32_t dst = smb + OB;
#pragma unroll
        for (int c = 0; c < 4; c++) {
            uint32_t off = rld * 128 + (cb + c) * 16;
            cpa16(dst + SWZ(off), src + c * 16);
        }
        asm volatile("cp.async.commit_group;" ::: "memory");
    }

    const uint32_t lm_off0 = SWZ((uint32_t)((lane & 7) * 128 + (lane >> 3) * 16));
    const uint32_t lm_off1 = SWZ((uint32_t)((lane & 7) * 128 + 64 + (lane >> 3) * 16));

    float vmax0, vsum0, vmax1, vsum1;
    float C[16][4];
    uint32_t b[4][8];

#define PREFETCH(tt) do {                                                          \
    const char* _src = (const char*)(g_B16 + (size_t)(nbase + (tt) * NT + rld) * D) + cb * 16; \
    uint32_t _dst = smb + OB + ((tt) & 1) * 16384;                                 \
    _Pragma("unroll")                                                              \
    for (int c = 0; c < 4; c++) {                                                  \
        uint32_t off = rld * 128 + (cb + c) * 16;                                  \
        cpa16(_dst + SWZ(off), _src + c * 16);                                     \
    }                                                                              \
    asm volatile("cp.async.commit_group;" ::: "memory");                           \
} while (0)

#define CHUNK_MMA(ng, bB) do {                                                     \
    _Pragma("unroll")                                                              \
    for (int j = 0; j < 4; j++) {                                                  \
        uint32_t nb = ((ng) * 4 + j) * 1024;                                       \
        ldsm4(b[j][0], b[j][1], b[j][2], b[j][3], (bB) + nb + lm_off0);            \
        ldsm4(b[j][4], b[j][5], b[j][6], b[j][7], (bB) + nb + lm_off1);            \
    }                                                                              \
    _Pragma("unroll")                                                              \
    for (int ks = 0; ks < 4; ks++)                                                 \
        _Pragma("unroll")                                                          \
        for (int j = 0; j < 4; j++)                                                \
            mma16816(C[(ng) * 4 + j], A[ks], b[j][2 * ks], b[j][2 * ks + 1]);      \
} while (0)

    // epilogue chunk: add q, track max, accumulate ex2 sums vs constant reference
#define CHUNK_EPI(ng, t) do {                                                      \
    _Pragma("unroll")                                                              \
    for (int j = 0; j < 4; j++) {                                                  \
        int ns = (ng) * 4 + j;                                                     \
        float2 q = *(const float2*)(sQ + (t) * NT + ns * 8 + 2 * tc);              \
        float v0 = C[ns][0] + q.x, v1 = C[ns][1] + q.y;                            \
        float v2 = C[ns][2] + q.x, v3 = C[ns][3] + q.y;                            \
        tmax0 = fmaxf(tmax0, fmaxf(v0, v1));                                       \
        tmax1 = fmaxf(tmax1, fmaxf(v2, v3));                                       \
        s0a += ex2f(v0 - rm0); s0b += ex2f(v1 - rm0);                              \
        s1a += ex2f(v2 - rm1); s1b += ex2f(v3 - rm1);                              \
    }                                                                              \
} while (0)

    // ---------------- tile 0 prologue (max-first epilogue) ----------------
    {
        asm volatile("cp.async.wait_group 0;" ::: "memory");
        __syncthreads();
        PREFETCH(1);
        const uint32_t bB = smb + OB;
#pragma unroll
        for (int ns = 0; ns < 16; ns++) {
            C[ns][0] = 0.f; C[ns][1] = 0.f; C[ns][2] = 0.f; C[ns][3] = 0.f;
        }
        CHUNK_MMA(0, bB); CHUNK_MMA(1, bB); CHUNK_MMA(2, bB); CHUNK_MMA(3, bB);

        float tmax0 = -3.0e38f, tmax1 = -3.0e38f;
#pragma unroll
        for (int ns = 0; ns < 16; ns++) {
            float2 q = *(const float2*)(sQ + ns * 8 + 2 * tc);
            C[ns][0] += q.x; C[ns][1] += q.y;
            C[ns][2] += q.x; C[ns][3] += q.y;
            tmax0 = fmaxf(tmax0, fmaxf(C[ns][0], C[ns][1]));
            tmax1 = fmaxf(tmax1, fmaxf(C[ns][2], C[ns][3]));
        }
        vmax0 = tmax0; vmax1 = tmax1;
        float s0a = 0.f, s0b = 0.f, s1a = 0.f, s1b = 0.f;
#pragma unroll
        for (int ns = 0; ns < 16; ns += 2) {
            s0a += ex2f(C[ns][0] - vmax0) + ex2f(C[ns][1] - vmax0);
            s0b += ex2f(C[ns + 1][0] - vmax0) + ex2f(C[ns + 1][1] - vmax0);
            s1a += ex2f(C[ns][2] - vmax1) + ex2f(C[ns][3] - vmax1);
            s1b += ex2f(C[ns + 1][2] - vmax1) + ex2f(C[ns + 1][3] - vmax1);
        }
        vsum0 = s0a + s0b; vsum1 = s1a + s1b;
    }

    // ---------------- tiles 1..63: MMA with interleaved epilogue ----------------
#pragma unroll 1
    for (int t = 1; t < NTILES; t++) {
        asm volatile("cp.async.wait_group 0;" ::: "memory");
        __syncthreads();
        if (t + 1 < NTILES) PREFETCH(t + 1);
        const uint32_t bB = smb + OB + (t & 1) * 16384;

        const float rm0 = vmax0, rm1 = vmax1;
        float tmax0 = -3.0e38f, tmax1 = -3.0e38f;
        float s0a = 0.f, s0b = 0.f, s1a = 0.f, s1b = 0.f;

        // zero accumulators, then mma chunk ng interleaved with epi chunk ng-1
#pragma unroll
        for (int ns = 0; ns < 16; ns++) {
            C[ns][0] = 0.f; C[ns][1] = 0.f; C[ns][2] = 0.f; C[ns][3] = 0.f;
        }
        CHUNK_MMA(0, bB);
        CHUNK_MMA(1, bB);  CHUNK_EPI(0, t);
        CHUNK_MMA(2, bB);  CHUNK_EPI(1, t);
        CHUNK_MMA(3, bB);  CHUNK_EPI(2, t);
        CHUNK_EPI(3, t);

        // per-tile renorm (s relative to rm)
        float nm0 = fmaxf(rm0, tmax0);
        float nm1 = fmaxf(rm1, tmax1);
        vsum0 = (vsum0 + s0a + s0b) * ex2f(rm0 - nm0);
        vsum1 = (vsum1 + s1a + s1b) * ex2f(rm1 - nm1);
        vmax0 = nm0; vmax1 = nm1;
    }

    // combine 4 lanes (tc = 0..3) holding the same rows
#pragma unroll
    for (int off = 1; off <= 2; off <<= 1) {
        float omx0 = __shfl_xor_sync(0xffffffffu, vmax0, off);
        float osm0 = __shfl_xor_sync(0xffffffffu, vsum0, off);
        float omx1 = __shfl_xor_sync(0xffffffffu, vmax1, off);
        float osm1 = __shfl_xor_sync(0xffffffffu, vsum1, off);
        float nm0 = fmaxf(vmax0, omx0);
        vsum0 = vsum0 * ex2f(vmax0 - nm0) + osm0 * ex2f(omx0 - nm0);
        vmax0 = nm0;
        float nm1 = fmaxf(vmax1, omx1);
        vsum1 = vsum1 * ex2f(vmax1 - nm1) + osm1 * ex2f(omx1 - nm1);
        vmax1 = nm1;
    }

    if (tc == 0) {
        int r0 = m0 + wid * 16 + g;
        g_pmax[(size_t)r0 * 2 + half] = vmax0;
        g_psum[(size_t)r0 * 2 + half] = vsum0;
        g_pmax[(size_t)(r0 + 8) * 2 + half] = vmax1;
        g_psum[(size_t)(r0 + 8) * 2 + half] = vsum1;
    }
}

// ---------------- final combine ----------------
__global__ void kde_final(float* __restrict__ out) {
    int r = blockIdx.x * blockDim.x + threadIdx.x;
    if (r < M_ROWS) {
        float m0 = g_pmax[r * 2 + 0], s0 = g_psum[r * 2 + 0];
        float m1 = g_pmax[r * 2 + 1], s1 = g_psum[r * 2 + 1];
        float m = fmaxf(m0, m1);
        float s = s0 * ex2f(m0 - m) + s1 * ex2f(m1 - m);
        out[r] = g_cm[r] + LN2F * m + logf(s) - g_logW;
    }
}

// ---------------------------------------------------------------------------
extern "C" void kernel_launch(void* const* d_in, const int* in_sizes, int n_in,
                              void* d_out, int out_size) {
    const float* testX  = (const float*)d_in[0];
    const float* trainX = (const float*)d_in[1];
    const float* w      = (const float*)d_in[2];
    float* out = (float*)d_out;

    static int smem_set = 0;
    if (!smem_set) {
        cudaFuncSetAttribute(kde_main, cudaFuncAttributeMaxDynamicSharedMemorySize, SMEM_BYTES);
        smem_set = 1;
    }

    kde_pre<<<((M_ROWS + N_ROWS) * 4 + 255) / 256, 256>>>(testX, trainX, w);
    kde_pre_wsum<<<1, 256>>>(w, N_ROWS);
    kde_main<<<128, 256, SMEM_BYTES>>>();
    kde_final<<<(M_ROWS + 255) / 256, 256>>>(out);
}

// round 9
// speedup vs baseline: 7.1792x; 1.1515x over previous
#include <cuda_runtime.h>
#include <cuda_fp16.h>
#include <math.h>
#include <stdint.h>

// Gaussian KDE log-likelihood via warp-level fp16 mma.sync + fused log2-domain
// logsumexp. 1024 CTAs (64 mtiles x 16 n-slices), 2 CTAs/SM, chunked C-buffer
// pipeline. Baseline PTX only (compute_103-safe).

#define D      64
#define ZCONST 58.812066125099045f
#define LOG2E  1.4426950408889634f
#define LN2F   0.6931471805599453f

#define M_ROWS 8192
#define N_ROWS 16384
#define MT     128
#define NT     128
#define NSLICES 16
#define SLICE_N 1024
#define TILES_PER 8          // SLICE_N / NT

// ---------------- device scratch ----------------
__device__ __half g_A16[M_ROWS * D];   // test * log2e
__device__ __half g_B16[N_ROWS * D];   // train
__device__ float g_cm[M_ROWS];
__device__ float g_q2[N_ROWS];
__device__ float g_logW;
__device__ float g_pmax[M_ROWS * NSLICES];
__device__ float g_psum[M_ROWS * NSLICES];

// ---------------- helpers ----------------
__device__ __forceinline__ uint32_t smem_u32(const void* p) {
    uint32_t a;
    asm("{ .reg .u64 t; cvta.to.shared.u64 t, %1; cvt.u32.u64 %0, t; }" : "=r"(a) : "l"(p));
    return a;
}
__device__ __forceinline__ float ex2f(float x) {
    float r; asm("ex2.approx.f32 %0, %1;" : "=f"(r) : "f"(x)); return r;
}
__device__ __forceinline__ void cpa16(uint32_t dst, const void* src) {
    asm volatile("cp.async.cg.shared.global [%0], [%1], 16;" :: "r"(dst), "l"(src));
}
__device__ __forceinline__ void ldsm4(uint32_t& r0, uint32_t& r1, uint32_t& r2,
                                      uint32_t& r3, uint32_t addr) {
    asm volatile("ldmatrix.sync.aligned.m8n8.x4.shared.b16 {%0,%1,%2,%3}, [%4];"
                 : "=r"(r0), "=r"(r1), "=r"(r2), "=r"(r3) : "r"(addr));
}
__device__ __forceinline__ void mma16816(float* c, const uint32_t* a,
                                         uint32_t b0, uint32_t b1) {
    asm volatile("mma.sync.aligned.m16n8k16.row.col.f32.f16.f16.f32 "
                 "{%0,%1,%2,%3}, {%4,%5,%6,%7}, {%8,%9}, {%0,%1,%2,%3};"
                 : "+f"(c[0]), "+f"(c[1]), "+f"(c[2]), "+f"(c[3])
                 : "r"(a[0]), "r"(a[1]), "r"(a[2]), "r"(a[3]), "r"(b0), "r"(b1));
}
#define SWZ(o) ((o) ^ (((o) >> 3) & 0x70))

// ---------------- pre-kernels ----------------
__global__ void kde_pre(const float* __restrict__ testX,
                        const float* __restrict__ trainX,
                        const float* __restrict__ w) {
    int gt = blockIdx.x * blockDim.x + threadIdx.x;
    int row = gt >> 2;
    int part = gt & 3;
    bool is_test = row < M_ROWS;
    int r = is_test ? row : row - M_ROWS;
    if (!is_test && r >= N_ROWS) return;

    const float* src = (is_test ? testX : trainX) + (size_t)r * D + part * 16;
    float4 v[4];
    float s = 0.f;
#pragma unroll
    for (int j = 0; j < 4; j++) {
        v[j] = *(const float4*)(src + j * 4);
        s += v[j].x * v[j].x + v[j].y * v[j].y + v[j].z * v[j].z + v[j].w * v[j].w;
    }
    s += __shfl_xor_sync(0xffffffffu, s, 1);
    s += __shfl_xor_sync(0xffffffffu, s, 2);

    const float scale = is_test ? LOG2E : 1.0f;
    __half* dst = (is_test ? g_A16 : g_B16) + (size_t)r * D + part * 16;
#pragma unroll
    for (int j = 0; j < 4; j++) {
        float xs[4] = {v[j].x, v[j].y, v[j].z, v[j].w};
#pragma unroll
        for (int c = 0; c < 4; c++)
            dst[j * 4 + c] = __float2half_rn(xs[c] * scale);
    }
    if (part == 0) {
        if (is_test) g_cm[r] = -0.5f * s - ZCONST;
        else         g_q2[r] = (logf(fmaxf(w[r], 1e-37f)) - 0.5f * s) * LOG2E;
    }
}

__global__ void kde_pre_wsum(const float* __restrict__ w, int N) {
    __shared__ float red[256];
    float s = 0.f;
    for (int j = threadIdx.x; j < N; j += 256) s += w[j];
    red[threadIdx.x] = s;
    __syncthreads();
#pragma unroll
    for (int o = 128; o > 0; o >>= 1) {
        if (threadIdx.x < o) red[threadIdx.x] += red[threadIdx.x + o];
        __syncthreads();
    }
    if (threadIdx.x == 0) g_logW = logf(red[0]);
}

// ---------------- main kernel ----------------
// dyn smem: [0, 4KB) q2 slice ; [4KB, 36KB) B tiles: buf*16384
#define OB 4096
#define SMEM_BYTES 36864

__global__ __launch_bounds__(256, 2) void kde_main() {
    extern __shared__ char sm[];
    float* sQ = (float*)sm;
    const uint32_t smb = smem_u32(sm);

    const int tid  = threadIdx.x;
    const int wid  = tid >> 5;
    const int lane = tid & 31;
    const int g    = lane >> 2;
    const int tc   = lane & 3;
    const int mtile = blockIdx.x >> 4;
    const int slice = blockIdx.x & 15;
    const int m0 = mtile * MT;
    const int nbase = slice * SLICE_N;

    // preload q2 slice into smem (1 float4 per thread)
    {
        const float4* qs = (const float4*)(g_q2 + nbase);
        ((float4*)sQ)[tid] = qs[tid];
    }

    // resident A fragments (rows m0 + wid*16 + {g, g+8})
    uint32_t A[4][4];
    {
        size_t base = (size_t)(m0 + wid * 16 + g) * D + 2 * tc;
#pragma unroll
        for (int ks = 0; ks < 4; ks++) {
            size_t o = base + ks * 16;
            A[ks][0] = *(const uint32_t*)(g_A16 + o);
            A[ks][1] = *(const uint32_t*)(g_A16 + o + 8 * D);
            A[ks][2] = *(const uint32_t*)(g_A16 + o + 8);
            A[ks][3] = *(const uint32_t*)(g_A16 + o + 8 * D + 8);
        }
    }

    // B tile loader: 2 threads per row, 4 x 16B chunks each
    const int rld = tid >> 1;
    const int cb  = (tid & 1) * 4;

#define PREFETCH(tt) do {                                                          \
    const char* _src = (const char*)(g_B16 + (size_t)(nbase + (tt) * NT + rld) * D) + cb * 16; \
    uint32_t _dst = smb + OB + ((tt) & 1) * 16384;                                 \
    _Pragma("unroll")                                                              \
    for (int c = 0; c < 4; c++) {                                                  \
        uint32_t off = rld * 128 + (cb + c) * 16;                                  \
        cpa16(_dst + SWZ(off), _src + c * 16);                                     \
    }                                                                              \
    asm volatile("cp.async.commit_group;" ::: "memory");                           \
} while (0)

    PREFETCH(0);

    const uint32_t lm_off0 = SWZ((uint32_t)((lane & 7) * 128 + (lane >> 3) * 16));
    const uint32_t lm_off1 = SWZ((uint32_t)((lane & 7) * 128 + 64 + (lane >> 3) * 16));

    float vmax0, vsum0, vmax1, vsum1;
    float C0[4][4], C1[4][4];
    uint32_t b[4][8];

    // MMA for 4 ns-chunk into CB
#define CHUNK_MMA(CB, ng, bB) do {                                                 \
    _Pragma("unroll")                                                              \
    for (int j = 0; j < 4; j++) {                                                  \
        uint32_t nb = ((ng) * 4 + j) * 1024;                                       \
        ldsm4(b[j][0], b[j][1], b[j][2], b[j][3], (bB) + nb + lm_off0);            \
        ldsm4(b[j][4], b[j][5], b[j][6], b[j][7], (bB) + nb + lm_off1);            \
    }                                                                              \
    _Pragma("unroll")                                                              \
    for (int j = 0; j < 4; j++) {                                                  \
        (CB)[j][0] = 0.f; (CB)[j][1] = 0.f; (CB)[j][2] = 0.f; (CB)[j][3] = 0.f;    \
    }                                                                              \
    _Pragma("unroll")                                                              \
    for (int ks = 0; ks < 4; ks++)                                                 \
        _Pragma("unroll")                                                          \
        for (int j = 0; j < 4; j++)                                                \
            mma16816((CB)[j], A[ks], b[j][2 * ks], b[j][2 * ks + 1]);              \
} while (0)

    // epilogue for 4 ns-chunk vs constant reference max
#define CHUNK_EPI(CB, ng, t) do {                                                  \
    _Pragma("unroll")                                                              \
    for (int j = 0; j < 4; j++) {                                                  \
        int ns = (ng) * 4 + j;                                                     \
        float2 q = *(const float2*)(sQ + (t) * NT + ns * 8 + 2 * tc);              \
        float v0 = (CB)[j][0] + q.x, v1 = (CB)[j][1] + q.y;                        \
        float v2 = (CB)[j][2] + q.x, v3 = (CB)[j][3] + q.y;                        \
        tmax0 = fmaxf(tmax0, fmaxf(v0, v1));                                       \
        tmax1 = fmaxf(tmax1, fmaxf(v2, v3));                                       \
        s0 += ex2f(v0 - rm0) + ex2f(v1 - rm0);                                     \
        s1 += ex2f(v2 - rm1) + ex2f(v3 - rm1);                                     \
    }                                                                              \
} while (0)

    // ---------------- tile 0 (establishes vmax; small ref offset trick) ----------------
    {
        asm volatile("cp.async.wait_group 0;" ::: "memory");
        __syncthreads();
        PREFETCH(1);
        const uint32_t bB = smb + OB;

        // first chunk computed alone to get an initial reference
        float rm0, rm1, tmax0 = -3.0e38f, tmax1 = -3.0e38f;
        float s0 = 0.f, s1 = 0.f;

        CHUNK_MMA(C0, 0, bB);
        // max of chunk 0 as reference
        {
            float a0 = -3.0e38f, a1 = -3.0e38f;
#pragma unroll
            for (int j = 0; j < 4; j++) {
                float2 q = *(const float2*)(sQ + j * 8 + 2 * tc);
                C0[j][0] += q.x; C0[j][1] += q.y;
                C0[j][2] += q.x; C0[j][3] += q.y;
                a0 = fmaxf(a0, fmaxf(C0[j][0], C0[j][1]));
                a1 = fmaxf(a1, fmaxf(C0[j][2], C0[j][3]));
            }
            rm0 = a0; rm1 = a1; tmax0 = a0; tmax1 = a1;
#pragma unroll
            for (int j = 0; j < 4; j++) {
                s0 += ex2f(C0[j][0] - rm0) + ex2f(C0[j][1] - rm0);
                s1 += ex2f(C0[j][2] - rm1) + ex2f(C0[j][3] - rm1);
            }
        }
        CHUNK_MMA(C1, 1, bB);
        CHUNK_MMA(C0, 2, bB);  CHUNK_EPI(C1, 1, 0);
        CHUNK_MMA(C1, 3, bB);  CHUNK_EPI(C0, 2, 0);
        CHUNK_EPI(C1, 3, 0);

        float nm0 = fmaxf(rm0, tmax0), nm1 = fmaxf(rm1, tmax1);
        vsum0 = s0 * ex2f(rm0 - nm0);
        vsum1 = s1 * ex2f(rm1 - nm1);
        vmax0 = nm0; vmax1 = nm1;
    }

    // ---------------- tiles 1..7: fully interleaved ----------------
#pragma unroll 1
    for (int t = 1; t < TILES_PER; t++) {
        asm volatile("cp.async.wait_group 0;" ::: "memory");
        __syncthreads();
        if (t + 1 < TILES_PER) PREFETCH(t + 1);
        const uint32_t bB = smb + OB + (t & 1) * 16384;

        const float rm0 = vmax0, rm1 = vmax1;
        float tmax0 = -3.0e38f, tmax1 = -3.0e38f;
        float s0 = 0.f, s1 = 0.f;

        CHUNK_MMA(C0, 0, bB);
        CHUNK_MMA(C1, 1, bB);  CHUNK_EPI(C0, 0, t);
        CHUNK_MMA(C0, 2, bB);  CHUNK_EPI(C1, 1, t);
        CHUNK_MMA(C1, 3, bB);  CHUNK_EPI(C0, 2, t);
        CHUNK_EPI(C1, 3, t);

        float nm0 = fmaxf(rm0, tmax0), nm1 = fmaxf(rm1, tmax1);
        vsum0 = (vsum0 + s0) * ex2f(rm0 - nm0);
        vsum1 = (vsum1 + s1) * ex2f(rm1 - nm1);
        vmax0 = nm0; vmax1 = nm1;
    }

    // combine 4 lanes (tc = 0..3) holding the same rows
#pragma unroll
    for (int off = 1; off <= 2; off <<= 1) {
        float omx0 = __shfl_xor_sync(0xffffffffu, vmax0, off);
        float osm0 = __shfl_xor_sync(0xffffffffu, vsum0, off);
        float omx1 = __shfl_xor_sync(0xffffffffu, vmax1, off);
        float osm1 = __shfl_xor_sync(0xffffffffu, vsum1, off);
        float nm0 = fmaxf(vmax0, omx0);
        vsum0 = vsum0 * ex2f(vmax0 - nm0) + osm0 * ex2f(omx0 - nm0);
        vmax0 = nm0;
        float nm1 = fmaxf(vmax1, omx1);
        vsum1 = vsum1 * ex2f(vmax1 - nm1) + osm1 * ex2f(omx1 - nm1);
        vmax1 = nm1;
    }

    if (tc == 0) {
        int r0 = m0 + wid * 16 + g;
        g_pmax[(size_t)r0 * NSLICES + slice] = vmax0;
        g_psum[(size_t)r0 * NSLICES + slice] = vsum0;
        g_pmax[(size_t)(r0 + 8) * NSLICES + slice] = vmax1;
        g_psum[(size_t)(r0 + 8) * NSLICES + slice] = vsum1;
    }
}

// ---------------- final combine (fixed order over 16 slices) ----------------
__global__ void kde_final(float* __restrict__ out) {
    int r = blockIdx.x * blockDim.x + threadIdx.x;
    if (r < M_ROWS) {
        const float* pm = g_pmax + (size_t)r * NSLICES;
        const float* ps = g_psum + (size_t)r * NSLICES;
        float m = pm[0];
#pragma unroll
        for (int i = 1; i < NSLICES; i++) m = fmaxf(m, pm[i]);
        float s = 0.f;
#pragma unroll
        for (int i = 0; i < NSLICES; i++) s += ps[i] * ex2f(pm[i] - m);
        out[r] = g_cm[r] + LN2F * m + logf(s) - g_logW;
    }
}

// ---------------------------------------------------------------------------
extern "C" void kernel_launch(void* const* d_in, const int* in_sizes, int n_in,
                              void* d_out, int out_size) {
    const float* testX  = (const float*)d_in[0];
    const float* trainX = (const float*)d_in[1];
    const float* w      = (const float*)d_in[2];
    float* out = (float*)d_out;

    static int smem_set = 0;
    if (!smem_set) {
        cudaFuncSetAttribute(kde_main, cudaFuncAttributeMaxDynamicSharedMemorySize, SMEM_BYTES);
        smem_set = 1;
    }

    kde_pre<<<((M_ROWS + N_ROWS) * 4 + 255) / 256, 256>>>(testX, trainX, w);
    kde_pre_wsum<<<1, 256>>>(w, N_ROWS);
    kde_main<<<M_ROWS / MT * NSLICES, 256, SMEM_BYTES>>>();
    kde_final<<<(M_ROWS + 255) / 256, 256>>>(out);
}

// round 10
// speedup vs baseline: 7.7152x; 1.0747x over previous
#include <cuda_runtime.h>
#include <cuda_fp16.h>
#include <math.h>
#include <stdint.h>

// Gaussian KDE log-likelihood via warp-level fp16 mma.sync + direct biased
// 2^v accumulation (no max tracking; +64 log2-bias keeps everything in fp32
// range). 2048 CTAs (64 mtiles x 32 n-slices), 2 CTAs/SM.
// Baseline PTX only (compute_103-safe).

#define D      64
#define ZCONST 58.812066125099045f
#define LOG2E  1.4426950408889634f
#define LN2F   0.6931471805599453f
#define QBIAS  64.0f

#define M_ROWS 8192
#define N_ROWS 16384
#define MT     128
#define NT     128
#define NSLICES 32
#define SLICE_N 512
#define TILES_PER 4          // SLICE_N / NT

// ---------------- device scratch ----------------
__device__ __half g_A16[M_ROWS * D];   // test * log2e
__device__ __half g_B16[N_ROWS * D];   // train
__device__ float g_cm[M_ROWS];
__device__ float g_q2[N_ROWS];         // (ln w - 0.5||y||^2)*log2e + QBIAS
__device__ float g_logW;
__device__ float g_psum[M_ROWS * NSLICES];

// ---------------- helpers ----------------
__device__ __forceinline__ uint32_t smem_u32(const void* p) {
    uint32_t a;
    asm("{ .reg .u64 t; cvta.to.shared.u64 t, %1; cvt.u32.u64 %0, t; }" : "=r"(a) : "l"(p));
    return a;
}
__device__ __forceinline__ float ex2f(float x) {
    float r; asm("ex2.approx.f32 %0, %1;" : "=f"(r) : "f"(x)); return r;
}
__device__ __forceinline__ void cpa16(uint32_t dst, const void* src) {
    asm volatile("cp.async.cg.shared.global [%0], [%1], 16;" :: "r"(dst), "l"(src));
}
__device__ __forceinline__ void ldsm4(uint32_t& r0, uint32_t& r1, uint32_t& r2,
                                      uint32_t& r3, uint32_t addr) {
    asm volatile("ldmatrix.sync.aligned.m8n8.x4.shared.b16 {%0,%1,%2,%3}, [%4];"
                 : "=r"(r0), "=r"(r1), "=r"(r2), "=r"(r3) : "r"(addr));
}
__device__ __forceinline__ void mma16816(float* c, const uint32_t* a,
                                         uint32_t b0, uint32_t b1) {
    asm volatile("mma.sync.aligned.m16n8k16.row.col.f32.f16.f16.f32 "
                 "{%0,%1,%2,%3}, {%4,%5,%6,%7}, {%8,%9}, {%0,%1,%2,%3};"
                 : "+f"(c[0]), "+f"(c[1]), "+f"(c[2]), "+f"(c[3])
                 : "r"(a[0]), "r"(a[1]), "r"(a[2]), "r"(a[3]), "r"(b0), "r"(b1));
}
#define SWZ(o) ((o) ^ (((o) >> 3) & 0x70))

// ---------------- pre-kernels ----------------
__global__ void kde_pre(const float* __restrict__ testX,
                        const float* __restrict__ trainX,
                        const float* __restrict__ w) {
    int gt = blockIdx.x * blockDim.x + threadIdx.x;
    int row = gt >> 2;
    int part = gt & 3;
    bool is_test = row < M_ROWS;
    int r = is_test ? row : row - M_ROWS;
    if (!is_test && r >= N_ROWS) return;

    const float* src = (is_test ? testX : trainX) + (size_t)r * D + part * 16;
    float4 v[4];
    float s = 0.f;
#pragma unroll
    for (int j = 0; j < 4; j++) {
        v[j] = *(const float4*)(src + j * 4);
        s += v[j].x * v[j].x + v[j].y * v[j].y + v[j].z * v[j].z + v[j].w * v[j].w;
    }
    s += __shfl_xor_sync(0xffffffffu, s, 1);
    s += __shfl_xor_sync(0xffffffffu, s, 2);

    const float scale = is_test ? LOG2E : 1.0f;
    __half* dst = (is_test ? g_A16 : g_B16) + (size_t)r * D + part * 16;
#pragma unroll
    for (int j = 0; j < 4; j++) {
        float xs[4] = {v[j].x, v[j].y, v[j].z, v[j].w};
#pragma unroll
        for (int c = 0; c < 4; c++)
            dst[j * 4 + c] = __float2half_rn(xs[c] * scale);
    }
    if (part == 0) {
        if (is_test) g_cm[r] = -0.5f * s - ZCONST;
        else         g_q2[r] = (logf(fmaxf(w[r], 1e-37f)) - 0.5f * s) * LOG2E + QBIAS;
    }
}

__global__ void kde_pre_wsum(const float* __restrict__ w, int N) {
    __shared__ float red[256];
    float s = 0.f;
    for (int j = threadIdx.x; j < N; j += 256) s += w[j];
    red[threadIdx.x] = s;
    __syncthreads();
#pragma unroll
    for (int o = 128; o > 0; o >>= 1) {
        if (threadIdx.x < o) red[threadIdx.x] += red[threadIdx.x + o];
        __syncthreads();
    }
    if (threadIdx.x == 0) g_logW = logf(red[0]);
}

// ---------------- main kernel ----------------
// dyn smem: [0, 2KB) q2 slice ; [2KB, 34KB) B tiles: buf*16384
#define OB 2048
#define SMEM_BYTES 34816

__global__ __launch_bounds__(256, 2) void kde_main() {
    extern __shared__ char sm[];
    float* sQ = (float*)sm;
    const uint32_t smb = smem_u32(sm);

    const int tid  = threadIdx.x;
    const int wid  = tid >> 5;
    const int lane = tid & 31;
    const int g    = lane >> 2;
    const int tc   = lane & 3;
    const int mtile = blockIdx.x >> 5;
    const int slice = blockIdx.x & 31;
    const int m0 = mtile * MT;
    const int nbase = slice * SLICE_N;

    // preload q2 slice into smem (512 floats)
    if (tid < SLICE_N / 4)
        ((float4*)sQ)[tid] = ((const float4*)(g_q2 + nbase))[tid];

    // resident A fragments (rows m0 + wid*16 + {g, g+8})
    uint32_t A[4][4];
    {
        size_t base = (size_t)(m0 + wid * 16 + g) * D + 2 * tc;
#pragma unroll
        for (int ks = 0; ks < 4; ks++) {
            size_t o = base + ks * 16;
            A[ks][0] = *(const uint32_t*)(g_A16 + o);
            A[ks][1] = *(const uint32_t*)(g_A16 + o + 8 * D);
            A[ks][2] = *(const uint32_t*)(g_A16 + o + 8);
            A[ks][3] = *(const uint32_t*)(g_A16 + o + 8 * D + 8);
        }
    }

    // B tile loader: 2 threads per row, 4 x 16B chunks each
    const int rld = tid >> 1;
    const int cb  = (tid & 1) * 4;

#define PREFETCH(tt) do {                                                          \
    const char* _src = (const char*)(g_B16 + (size_t)(nbase + (tt) * NT + rld) * D) + cb * 16; \
    uint32_t _dst = smb + OB + ((tt) & 1) * 16384;                                 \
    _Pragma("unroll")                                                              \
    for (int c = 0; c < 4; c++) {                                                  \
        uint32_t off = rld * 128 + (cb + c) * 16;                                  \
        cpa16(_dst + SWZ(off), _src + c * 16);                                     \
    }                                                                              \
    asm volatile("cp.async.commit_group;" ::: "memory");                           \
} while (0)

    PREFETCH(0);

    const uint32_t lm_off0 = SWZ((uint32_t)((lane & 7) * 128 + (lane >> 3) * 16));
    const uint32_t lm_off1 = SWZ((uint32_t)((lane & 7) * 128 + 64 + (lane >> 3) * 16));

    float s0a = 0.f, s0b = 0.f, s1a = 0.f, s1b = 0.f;
    float C0[4][4], C1[4][4];
    uint32_t b[4][8];

#define CHUNK_MMA(CB, ng, bB) do {                                                 \
    _Pragma("unroll")                                                              \
    for (int j = 0; j < 4; j++) {                                                  \
        uint32_t nb = ((ng) * 4 + j) * 1024;                                       \
        ldsm4(b[j][0], b[j][1], b[j][2], b[j][3], (bB) + nb + lm_off0);            \
        ldsm4(b[j][4], b[j][5], b[j][6], b[j][7], (bB) + nb + lm_off1);            \
    }                                                                              \
    _Pragma("unroll")                                                              \
    for (int j = 0; j < 4; j++) {                                                  \
        (CB)[j][0] = 0.f; (CB)[j][1] = 0.f; (CB)[j][2] = 0.f; (CB)[j][3] = 0.f;    \
    }                                                                              \
    _Pragma("unroll")                                                              \
    for (int ks = 0; ks < 4; ks++)                                                 \
        _Pragma("unroll")                                                          \
        for (int j = 0; j < 4; j++)                                                \
            mma16816((CB)[j], A[ks], b[j][2 * ks], b[j][2 * ks + 1]);              \
} while (0)

    // epilogue: biased direct accumulation, no max tracking
#define CHUNK_EPI(CB, ng, t) do {                                                  \
    _Pragma("unroll")                                                              \
    for (int j = 0; j < 4; j++) {                                                  \
        int ns = (ng) * 4 + j;                                                     \
        float2 q = *(const float2*)(sQ + (t) * NT + ns * 8 + 2 * tc);              \
        float v0 = (CB)[j][0] + q.x, v1 = (CB)[j][1] + q.y;                        \
        float v2 = (CB)[j][2] + q.x, v3 = (CB)[j][3] + q.y;                        \
        if (j & 1) { s0b += ex2f(v0) + ex2f(v1); s1b += ex2f(v2) + ex2f(v3); }     \
        else       { s0a += ex2f(v0) + ex2f(v1); s1a += ex2f(v2) + ex2f(v3); }     \
    }                                                                              \
} while (0)

#pragma unroll 1
    for (int t = 0; t < TILES_PER; t++) {
        asm volatile("cp.async.wait_group 0;" ::: "memory");
        __syncthreads();
        if (t + 1 < TILES_PER) PREFETCH(t + 1);
        const uint32_t bB = smb + OB + (t & 1) * 16384;

        CHUNK_MMA(C0, 0, bB);
        CHUNK_MMA(C1, 1, bB);  CHUNK_EPI(C0, 0, t);
        CHUNK_MMA(C0, 2, bB);  CHUNK_EPI(C1, 1, t);
        CHUNK_MMA(C1, 3, bB);  CHUNK_EPI(C0, 2, t);
        CHUNK_EPI(C1, 3, t);

        __syncthreads();
    }

    float vsum0 = (s0a + s0b);
    float vsum1 = (s1a + s1b);

    // combine 4 lanes (tc = 0..3) holding the same rows
#pragma unroll
    for (int off = 1; off <= 2; off <<= 1) {
        vsum0 += __shfl_xor_sync(0xffffffffu, vsum0, off);
        vsum1 += __shfl_xor_sync(0xffffffffu, vsum1, off);
    }

    if (tc == 0) {
        int r0 = m0 + wid * 16 + g;
        g_psum[(size_t)r0 * NSLICES + slice] = vsum0;
        g_psum[(size_t)(r0 + 8) * NSLICES + slice] = vsum1;
    }
}

// ---------------- final combine (fixed order over 32 slices) ----------------
__global__ void kde_final(float* __restrict__ out) {
    int r = blockIdx.x * blockDim.x + threadIdx.x;
    if (r < M_ROWS) {
        const float4* ps = (const float4*)(g_psum + (size_t)r * NSLICES);
        float s = 0.f;
#pragma unroll
        for (int i = 0; i < NSLICES / 4; i++) {
            float4 v = ps[i];
            s += (v.x + v.y) + (v.z + v.w);
        }
        out[r] = g_cm[r] + logf(s) - QBIAS * LN2F - g_logW;
    }
}

// ---------------------------------------------------------------------------
extern "C" void kernel_launch(void* const* d_in, const int* in_sizes, int n_in,
                              void* d_out, int out_size) {
    const float* testX  = (const float*)d_in[0];
    const float* trainX = (const float*)d_in[1];
    const float* w      = (const float*)d_in[2];
    float* out = (float*)d_out;

    static int smem_set = 0;
    if (!smem_set) {
        cudaFuncSetAttribute(kde_main, cudaFuncAttributeMaxDynamicSharedMemorySize, SMEM_BYTES);
        smem_set = 1;
    }

    kde_pre<<<((M_ROWS + N_ROWS) * 4 + 255) / 256, 256>>>(testX, trainX, w);
    kde_pre_wsum<<<1, 256>>>(w, N_ROWS);
    kde_main<<<M_ROWS / MT * NSLICES, 256, SMEM_BYTES>>>();
    kde_final<<<(M_ROWS + 255) / 256, 256>>>(out);
}

// round 11
// speedup vs baseline: 8.0639x; 1.0452x over previous
#include <cuda_runtime.h>
#include <cuda_fp16.h>
#include <math.h>
#include <stdint.h>

// Gaussian KDE log-likelihood via warp-level fp16 mma.sync + direct biased
// 2^v accumulation. 2048 CTAs (64 mtiles x 32 n-slices), 2 CTAs/SM.
// Baseline PTX only (compute_103-safe).

#define D      64
#define ZCONST 58.812066125099045f
#define LOG2E  1.4426950408889634f
#define LN2F   0.6931471805599453f
#define QBIAS  64.0f

#define M_ROWS 8192
#define N_ROWS 16384
#define MT     128
#define NT     128
#define NSLICES 32
#define SLICE_N 512
#define TILES_PER 4          // SLICE_N / NT

// ---------------- device scratch ----------------
__device__ __half g_A16[M_ROWS * D];   // test * log2e
__device__ __half g_B16[N_ROWS * D];   // train
__device__ float g_cm[M_ROWS];
__device__ float g_q2[N_ROWS];         // (ln w - 0.5||y||^2)*log2e + QBIAS
__device__ float g_logW;
__device__ float g_psum[NSLICES * M_ROWS];   // [slice][row] -> coalesced final

// ---------------- helpers ----------------
__device__ __forceinline__ uint32_t smem_u32(const void* p) {
    uint32_t a;
    asm("{ .reg .u64 t; cvta.to.shared.u64 t, %1; cvt.u32.u64 %0, t; }" : "=r"(a) : "l"(p));
    return a;
}
__device__ __forceinline__ float ex2f(float x) {
    float r; asm("ex2.approx.f32 %0, %1;" : "=f"(r) : "f"(x)); return r;
}
__device__ __forceinline__ void cpa16(uint32_t dst, const void* src) {
    asm volatile("cp.async.cg.shared.global [%0], [%1], 16;" :: "r"(dst), "l"(src));
}
__device__ __forceinline__ void ldsm4(uint32_t& r0, uint32_t& r1, uint32_t& r2,
                                      uint32_t& r3, uint32_t addr) {
    asm volatile("ldmatrix.sync.aligned.m8n8.x4.shared.b16 {%0,%1,%2,%3}, [%4];"
                 : "=r"(r0), "=r"(r1), "=r"(r2), "=r"(r3) : "r"(addr));
}
__device__ __forceinline__ void mma16816(float* c, const uint32_t* a,
                                         uint32_t b0, uint32_t b1) {
    asm volatile("mma.sync.aligned.m16n8k16.row.col.f32.f16.f16.f32 "
                 "{%0,%1,%2,%3}, {%4,%5,%6,%7}, {%8,%9}, {%0,%1,%2,%3};"
                 : "+f"(c[0]), "+f"(c[1]), "+f"(c[2]), "+f"(c[3])
                 : "r"(a[0]), "r"(a[1]), "r"(a[2]), "r"(a[3]), "r"(b0), "r"(b1));
}
#define SWZ(o) ((o) ^ (((o) >> 3) & 0x70))

// ---------------- pre-kernel (conversion + norms + fused wsum) ----------------
__global__ void kde_pre(const float* __restrict__ testX,
                        const float* __restrict__ trainX,
                        const float* __restrict__ w) {
    if (blockIdx.x == gridDim.x - 1) {
        // fused deterministic weight-sum block
        __shared__ float red[256];
        float s = 0.f;
        for (int j = threadIdx.x; j < N_ROWS; j += 256) s += w[j];
        red[threadIdx.x] = s;
        __syncthreads();
#pragma unroll
        for (int o = 128; o > 0; o >>= 1) {
            if (threadIdx.x < o) red[threadIdx.x] += red[threadIdx.x + o];
            __syncthreads();
        }
        if (threadIdx.x == 0) g_logW = logf(red[0]);
        return;
    }

    int gt = blockIdx.x * blockDim.x + threadIdx.x;
    int row = gt >> 2;
    int part = gt & 3;
    bool is_test = row < M_ROWS;
    int r = is_test ? row : row - M_ROWS;
    if (!is_test && r >= N_ROWS) return;

    const float* src = (is_test ? testX : trainX) + (size_t)r * D + part * 16;
    float4 v[4];
    float s = 0.f;
#pragma unroll
    for (int j = 0; j < 4; j++) {
        v[j] = *(const float4*)(src + j * 4);
        s += v[j].x * v[j].x + v[j].y * v[j].y + v[j].z * v[j].z + v[j].w * v[j].w;
    }
    s += __shfl_xor_sync(0xffffffffu, s, 1);
    s += __shfl_xor_sync(0xffffffffu, s, 2);

    const float scale = is_test ? LOG2E : 1.0f;
    __half* dst = (is_test ? g_A16 : g_B16) + (size_t)r * D + part * 16;
#pragma unroll
    for (int j = 0; j < 4; j++) {
        float xs[4] = {v[j].x, v[j].y, v[j].z, v[j].w};
#pragma unroll
        for (int c = 0; c < 4; c++)
            dst[j * 4 + c] = __float2half_rn(xs[c] * scale);
    }
    if (part == 0) {
        if (is_test) g_cm[r] = -0.5f * s - ZCONST;
        else         g_q2[r] = (logf(fmaxf(w[r], 1e-37f)) - 0.5f * s) * LOG2E + QBIAS;
    }
}

// ---------------- main kernel ----------------
// dyn smem: [0, 2KB) q2 slice ; [2KB, 34KB) B tiles: buf*16384
#define OB 2048
#define SMEM_BYTES 34816

__global__ __launch_bounds__(256, 2) void kde_main() {
    extern __shared__ char sm[];
    float* sQ = (float*)sm;
    const uint32_t smb = smem_u32(sm);

    const int tid  = threadIdx.x;
    const int wid  = tid >> 5;
    const int lane = tid & 31;
    const int g    = lane >> 2;
    const int tc   = lane & 3;
    const int mtile = blockIdx.x >> 5;
    const int slice = blockIdx.x & 31;
    const int m0 = mtile * MT;
    const int nbase = slice * SLICE_N;

    // hoisted A-fragment loads (L2 hits after first slice-CTA of this mtile)
    uint32_t A[4][4];
    {
        size_t base = (size_t)(m0 + wid * 16 + g) * D + 2 * tc;
#pragma unroll
        for (int ks = 0; ks < 4; ks++) {
            size_t o = base + ks * 16;
            A[ks][0] = *(const uint32_t*)(g_A16 + o);
            A[ks][1] = *(const uint32_t*)(g_A16 + o + 8 * D);
            A[ks][2] = *(const uint32_t*)(g_A16 + o + 8);
            A[ks][3] = *(const uint32_t*)(g_A16 + o + 8 * D + 8);
        }
    }

    // preload q2 slice into smem (512 floats)
    if (tid < SLICE_N / 4)
        ((float4*)sQ)[tid] = ((const float4*)(g_q2 + nbase))[tid];

    // B tile loader: 2 threads per row, 4 x 16B chunks each
    const int rld = tid >> 1;
    const int cb  = (tid & 1) * 4;

#define PREFETCH(tt) do {                                                          \
    const char* _src = (const char*)(g_B16 + (size_t)(nbase + (tt) * NT + rld) * D) + cb * 16; \
    uint32_t _dst = smb + OB + ((tt) & 1) * 16384;                                 \
    _Pragma("unroll")                                                              \
    for (int c = 0; c < 4; c++) {                                                  \
        uint32_t off = rld * 128 + (cb + c) * 16;                                  \
        cpa16(_dst + SWZ(off), _src + c * 16);                                     \
    }                                                                              \
    asm volatile("cp.async.commit_group;" ::: "memory");                           \
} while (0)

    PREFETCH(0);

    const uint32_t lm_off0 = SWZ((uint32_t)((lane & 7) * 128 + (lane >> 3) * 16));
    const uint32_t lm_off1 = SWZ((uint32_t)((lane & 7) * 128 + 64 + (lane >> 3) * 16));

    float s0a = 0.f, s0b = 0.f, s1a = 0.f, s1b = 0.f;
    float C0[4][4], C1[4][4];
    uint32_t b[4][8];

#define CHUNK_MMA(CB, ng, bB) do {                                                 \
    _Pragma("unroll")                                                              \
    for (int j = 0; j < 4; j++) {                                                  \
        uint32_t nb = ((ng) * 4 + j) * 1024;                                       \
        ldsm4(b[j][0], b[j][1], b[j][2], b[j][3], (bB) + nb + lm_off0);            \
        ldsm4(b[j][4], b[j][5], b[j][6], b[j][7], (bB) + nb + lm_off1);            \
    }                                                                              \
    _Pragma("unroll")                                                              \
    for (int j = 0; j < 4; j++) {                                                  \
        (CB)[j][0] = 0.f; (CB)[j][1] = 0.f; (CB)[j][2] = 0.f; (CB)[j][3] = 0.f;    \
    }                                                                              \
    _Pragma("unroll")                                                              \
    for (int ks = 0; ks < 4; ks++)                                                 \
        _Pragma("unroll")                                                          \
        for (int j = 0; j < 4; j++)                                                \
            mma16816((CB)[j], A[ks], b[j][2 * ks], b[j][2 * ks + 1]);              \
} while (0)

#define CHUNK_EPI(CB, ng, t) do {                                                  \
    _Pragma("unroll")                                                              \
    for (int j = 0; j < 4; j++) {                                                  \
        int ns = (ng) * 4 + j;                                                     \
        float2 q = *(const float2*)(sQ + (t) * NT + ns * 8 + 2 * tc);              \
        float v0 = (CB)[j][0] + q.x, v1 = (CB)[j][1] + q.y;                        \
        float v2 = (CB)[j][2] + q.x, v3 = (CB)[j][3] + q.y;                        \
        if (j & 1) { s0b += ex2f(v0) + ex2f(v1); s1b += ex2f(v2) + ex2f(v3); }     \
        else       { s0a += ex2f(v0) + ex2f(v1); s1a += ex2f(v2) + ex2f(v3); }     \
    }                                                                              \
} while (0)

#pragma unroll 1
    for (int t = 0; t < TILES_PER; t++) {
        asm volatile("cp.async.wait_group 0;" ::: "memory");
        __syncthreads();   // sole barrier per tile: also orders buf reuse + sQ on t=0
        if (t + 1 < TILES_PER) PREFETCH(t + 1);
        const uint32_t bB = smb + OB + (t & 1) * 16384;

        CHUNK_MMA(C0, 0, bB);
        CHUNK_MMA(C1, 1, bB);  CHUNK_EPI(C0, 0, t);
        CHUNK_MMA(C0, 2, bB);  CHUNK_EPI(C1, 1, t);
        CHUNK_MMA(C1, 3, bB);  CHUNK_EPI(C0, 2, t);
        CHUNK_EPI(C1, 3, t);
    }

    float vsum0 = (s0a + s0b);
    float vsum1 = (s1a + s1b);

    // combine 4 lanes (tc = 0..3) holding the same rows
#pragma unroll
    for (int off = 1; off <= 2; off <<= 1) {
        vsum0 += __shfl_xor_sync(0xffffffffu, vsum0, off);
        vsum1 += __shfl_xor_sync(0xffffffffu, vsum1, off);
    }

    if (tc == 0) {
        int r0 = m0 + wid * 16 + g;
        g_psum[(size_t)slice * M_ROWS + r0] = vsum0;
        g_psum[(size_t)slice * M_ROWS + r0 + 8] = vsum1;
    }
}

// ---------------- final combine ([slice][row]: coalesced, MLP 32) ----------------
__global__ void kde_final(float* __restrict__ out) {
    int r = blockIdx.x * blockDim.x + threadIdx.x;
    if (r < M_ROWS) {
        float p0 = 0.f, p1 = 0.f, p2 = 0.f, p3 = 0.f;
#pragma unroll
        for (int i = 0; i < NSLICES; i += 4) {
            p0 += g_psum[(size_t)(i + 0) * M_ROWS + r];
            p1 += g_psum[(size_t)(i + 1) * M_ROWS + r];
            p2 += g_psum[(size_t)(i + 2) * M_ROWS + r];
            p3 += g_psum[(size_t)(i + 3) * M_ROWS + r];
        }
        float s = (p0 + p1) + (p2 + p3);
        out[r] = g_cm[r] + logf(s) - QBIAS * LN2F - g_logW;
    }
}

// ---------------------------------------------------------------------------
extern "C" void kernel_launch(void* const* d_in, const int* in_sizes, int n_in,
                              void* d_out, int out_size) {
    const float* testX  = (const float*)d_in[0];
    const float* trainX = (const float*)d_in[1];
    const float* w      = (const float*)d_in[2];
    float* out = (float*)d_out;

    static int smem_set = 0;
    if (!smem_set) {
        cudaFuncSetAttribute(kde_main, cudaFuncAttributeMaxDynamicSharedMemorySize, SMEM_BYTES);
        smem_set = 1;
    }

    // 384 conversion blocks + 1 fused wsum block
    kde_pre<<<((M_ROWS + N_ROWS) * 4) / 256 + 1, 256>>>(testX, trainX, w);
    kde_main<<<M_ROWS / MT * NSLICES, 256, SMEM_BYTES>>>();
    kde_final<<<(M_ROWS + 127) / 128, 128>>>(out);
}

// round 12
// speedup vs baseline: 8.8413x; 1.0964x over previous
#include <cuda_runtime.h>
#include <cuda_fp16.h>
#include <math.h>
#include <stdint.h>

// Gaussian KDE log-likelihood via warp-level fp16 mma.sync + direct biased
// 2^v accumulation. 2048 CTAs (64 mtiles x 32 n-slices), 2 CTAs/SM.
// Baseline PTX only (compute_103-safe).

#define D      64
#define ZCONST 58.812066125099045f
#define LOG2E  1.4426950408889634f
#define LN2F   0.6931471805599453f
#define QBIAS  64.0f

#define M_ROWS 8192
#define N_ROWS 16384
#define MT     128
#define NT     128
#define NSLICES 32
#define SLICE_N 512
#define TILES_PER 4          // SLICE_N / NT

// ---------------- device scratch ----------------
__device__ __half g_A16[M_ROWS * D];   // test * log2e
__device__ __half g_B16[N_ROWS * D];   // train
__device__ float g_cm[M_ROWS];
__device__ float g_q2[N_ROWS];         // (ln w - 0.5||y||^2)*log2e + QBIAS
__device__ float g_logW;
__device__ float g_psum[NSLICES * M_ROWS];   // [slice][row] -> coalesced final

// ---------------- helpers ----------------
__device__ __forceinline__ uint32_t smem_u32(const void* p) {
    uint32_t a;
    asm("{ .reg .u64 t; cvta.to.shared.u64 t, %1; cvt.u32.u64 %0, t; }" : "=r"(a) : "l"(p));
    return a;
}
__device__ __forceinline__ float ex2f(float x) {
    float r; asm("ex2.approx.f32 %0, %1;" : "=f"(r) : "f"(x)); return r;
}
// packed f32x2 -> f16x2: low half = lo, high half = hi
__device__ __forceinline__ uint32_t f2h2(float lo, float hi) {
    uint32_t r;
    asm("cvt.rn.f16x2.f32 %0, %1, %2;" : "=r"(r) : "f"(hi), "f"(lo));
    return r;
}
__device__ __forceinline__ void cpa16(uint32_t dst, const void* src) {
    asm volatile("cp.async.cg.shared.global [%0], [%1], 16;" :: "r"(dst), "l"(src));
}
__device__ __forceinline__ void ldsm4(uint32_t& r0, uint32_t& r1, uint32_t& r2,
                                      uint32_t& r3, uint32_t addr) {
    asm volatile("ldmatrix.sync.aligned.m8n8.x4.shared.b16 {%0,%1,%2,%3}, [%4];"
                 : "=r"(r0), "=r"(r1), "=r"(r2), "=r"(r3) : "r"(addr));
}
__device__ __forceinline__ void mma16816(float* c, const uint32_t* a,
                                         uint32_t b0, uint32_t b1) {
    asm volatile("mma.sync.aligned.m16n8k16.row.col.f32.f16.f16.f32 "
                 "{%0,%1,%2,%3}, {%4,%5,%6,%7}, {%8,%9}, {%0,%1,%2,%3};"
                 : "+f"(c[0]), "+f"(c[1]), "+f"(c[2]), "+f"(c[3])
                 : "r"(a[0]), "r"(a[1]), "r"(a[2]), "r"(a[3]), "r"(b0), "r"(b1));
}
#define SWZ(o) ((o) ^ (((o) >> 3) & 0x70))

// ---------------- pre-kernel (conversion + norms + fused wsum) ----------------
__global__ void kde_pre(const float* __restrict__ testX,
                        const float* __restrict__ trainX,
                        const float* __restrict__ w) {
    if (blockIdx.x == gridDim.x - 1) {
        // fused deterministic weight-sum block
        __shared__ float red[256];
        float s = 0.f;
        for (int j = threadIdx.x; j < N_ROWS; j += 256) s += w[j];
        red[threadIdx.x] = s;
        __syncthreads();
#pragma unroll
        for (int o = 128; o > 0; o >>= 1) {
            if (threadIdx.x < o) red[threadIdx.x] += red[threadIdx.x + o];
            __syncthreads();
        }
        if (threadIdx.x == 0) g_logW = logf(red[0]);
        return;
    }

    int gt = blockIdx.x * blockDim.x + threadIdx.x;
    int row = gt >> 2;
    int part = gt & 3;
    bool is_test = row < M_ROWS;
    int r = is_test ? row : row - M_ROWS;
    if (!is_test && r >= N_ROWS) return;

    const float* src = (is_test ? testX : trainX) + (size_t)r * D + part * 16;
    float4 v[4];
    float s = 0.f;
#pragma unroll
    for (int j = 0; j < 4; j++) {
        v[j] = *(const float4*)(src + j * 4);
        s += v[j].x * v[j].x + v[j].y * v[j].y + v[j].z * v[j].z + v[j].w * v[j].w;
    }
    s += __shfl_xor_sync(0xffffffffu, s, 1);
    s += __shfl_xor_sync(0xffffffffu, s, 2);

    const float scale = is_test ? LOG2E : 1.0f;
    // packed conversion: 8 x cvt.rn.f16x2.f32, then 2 x STG.128
    uint32_t h[8];
#pragma unroll
    for (int j = 0; j < 4; j++) {
        h[2 * j]     = f2h2(v[j].x * scale, v[j].y * scale);
        h[2 * j + 1] = f2h2(v[j].z * scale, v[j].w * scale);
    }
    char* dst = (char*)(is_test ? g_A16 : g_B16) + (size_t)r * 128 + part * 32;
    ((uint4*)dst)[0] = make_uint4(h[0], h[1], h[2], h[3]);
    ((uint4*)dst)[1] = make_uint4(h[4], h[5], h[6], h[7]);

    if (part == 0) {
        if (is_test) g_cm[r] = -0.5f * s - ZCONST;
        else         g_q2[r] = (logf(fmaxf(w[r], 1e-37f)) - 0.5f * s) * LOG2E + QBIAS;
    }
}

// ---------------- main kernel ----------------
// dyn smem: [0, 2KB) q2 slice ; [2KB, 34KB) B tiles: buf*16384
#define OB 2048
#define SMEM_BYTES 34816

__global__ __launch_bounds__(256, 2) void kde_main() {
    extern __shared__ char sm[];
    float* sQ = (float*)sm;
    const uint32_t smb = smem_u32(sm);

    const int tid  = threadIdx.x;
    const int wid  = tid >> 5;
    const int lane = tid & 31;
    const int g    = lane >> 2;
    const int tc   = lane & 3;
    const int mtile = blockIdx.x >> 5;
    const int slice = blockIdx.x & 31;
    const int m0 = mtile * MT;
    const int nbase = slice * SLICE_N;

    // hoisted A-fragment loads (L2 hits after first slice-CTA of this mtile)
    uint32_t A[4][4];
    {
        size_t base = (size_t)(m0 + wid * 16 + g) * D + 2 * tc;
#pragma unroll
        for (int ks = 0; ks < 4; ks++) {
            size_t o = base + ks * 16;
            A[ks][0] = *(const uint32_t*)(g_A16 + o);
            A[ks][1] = *(const uint32_t*)(g_A16 + o + 8 * D);
            A[ks][2] = *(const uint32_t*)(g_A16 + o + 8);
            A[ks][3] = *(const uint32_t*)(g_A16 + o + 8 * D + 8);
        }
    }

    // preload q2 slice into smem (512 floats)
    if (tid < SLICE_N / 4)
        ((float4*)sQ)[tid] = ((const float4*)(g_q2 + nbase))[tid];

    // B tile loader: 2 threads per row, 4 x 16B chunks each
    const int rld = tid >> 1;
    const int cb  = (tid & 1) * 4;

#define PREFETCH(tt) do {                                                          \
    const char* _src = (const char*)(g_B16 + (size_t)(nbase + (tt) * NT + rld) * D) + cb * 16; \
    uint32_t _dst = smb + OB + ((tt) & 1) * 16384;                                 \
    _Pragma("unroll")                                                              \
    for (int c = 0; c < 4; c++) {                                                  \
        uint32_t off = rld * 128 + (cb + c) * 16;                                  \
        cpa16(_dst + SWZ(off), _src + c * 16);                                     \
    }                                                                              \
    asm volatile("cp.async.commit_group;" ::: "memory");                           \
} while (0)

    PREFETCH(0);

    const uint32_t lm_off0 = SWZ((uint32_t)((lane & 7) * 128 + (lane >> 3) * 16));
    const uint32_t lm_off1 = SWZ((uint32_t)((lane & 7) * 128 + 64 + (lane >> 3) * 16));

    float s0a = 0.f, s0b = 0.f, s1a = 0.f, s1b = 0.f;
    float C0[4][4], C1[4][4];
    uint32_t b[4][8];

#define CHUNK_MMA(CB, ng, bB) do {                                                 \
    _Pragma("unroll")                                                              \
    for (int j = 0; j < 4; j++) {                                                  \
        uint32_t nb = ((ng) * 4 + j) * 1024;                                       \
        ldsm4(b[j][0], b[j][1], b[j][2], b[j][3], (bB) + nb + lm_off0);            \
        ldsm4(b[j][4], b[j][5], b[j][6], b[j][7], (bB) + nb + lm_off1);            \
    }                                                                              \
    _Pragma("unroll")                                                              \
    for (int j = 0; j < 4; j++) {                                                  \
        (CB)[j][0] = 0.f; (CB)[j][1] = 0.f; (CB)[j][2] = 0.f; (CB)[j][3] = 0.f;    \
    }                                                                              \
    _Pragma("unroll")                                                              \
    for (int ks = 0; ks < 4; ks++)                                                 \
        _Pragma("unroll")                                                          \
        for (int j = 0; j < 4; j++)                                                \
            mma16816((CB)[j], A[ks], b[j][2 * ks], b[j][2 * ks + 1]);              \
} while (0)

#define CHUNK_EPI(CB, ng, t) do {                                                  \
    _Pragma("unroll")                                                              \
    for (int j = 0; j < 4; j++) {                                                  \
        int ns = (ng) * 4 + j;                                                     \
        float2 q = *(const float2*)(sQ + (t) * NT + ns * 8 + 2 * tc);              \
        float v0 = (CB)[j][0] + q.x, v1 = (CB)[j][1] + q.y;                        \
        float v2 = (CB)[j][2] + q.x, v3 = (CB)[j][3] + q.y;                        \
        if (j & 1) { s0b += ex2f(v0) + ex2f(v1); s1b += ex2f(v2) + ex2f(v3); }     \
        else       { s0a += ex2f(v0) + ex2f(v1); s1a += ex2f(v2) + ex2f(v3); }     \
    }                                                                              \
} while (0)

#pragma unroll 1
    for (int t = 0; t < TILES_PER; t++) {
        asm volatile("cp.async.wait_group 0;" ::: "memory");
        __syncthreads();   // sole barrier per tile: orders buf reuse + sQ on t=0
        if (t + 1 < TILES_PER) PREFETCH(t + 1);
        const uint32_t bB = smb + OB + (t & 1) * 16384;

        CHUNK_MMA(C0, 0, bB);
        CHUNK_MMA(C1, 1, bB);  CHUNK_EPI(C0, 0, t);
        CHUNK_MMA(C0, 2, bB);  CHUNK_EPI(C1, 1, t);
        CHUNK_MMA(C1, 3, bB);  CHUNK_EPI(C0, 2, t);
        CHUNK_EPI(C1, 3, t);
    }

    float vsum0 = (s0a + s0b);
    float vsum1 = (s1a + s1b);

    // combine 4 lanes (tc = 0..3) holding the same rows
#pragma unroll
    for (int off = 1; off <= 2; off <<= 1) {
        vsum0 += __shfl_xor_sync(0xffffffffu, vsum0, off);
        vsum1 += __shfl_xor_sync(0xffffffffu, vsum1, off);
    }

    if (tc == 0) {
        int r0 = m0 + wid * 16 + g;
        g_psum[(size_t)slice * M_ROWS + r0] = vsum0;
        g_psum[(size_t)slice * M_ROWS + r0 + 8] = vsum1;
    }
}

// ---------------- final combine ([slice][row]: coalesced, MLP 32) ----------------
__global__ void kde_final(float* __restrict__ out) {
    int r = blockIdx.x * blockDim.x + threadIdx.x;
    if (r < M_ROWS) {
        float p0 = 0.f, p1 = 0.f, p2 = 0.f, p3 = 0.f;
#pragma unroll
        for (int i = 0; i < NSLICES; i += 4) {
            p0 += g_psum[(size_t)(i + 0) * M_ROWS + r];
            p1 += g_psum[(size_t)(i + 1) * M_ROWS + r];
            p2 += g_psum[(size_t)(i + 2) * M_ROWS + r];
            p3 += g_psum[(size_t)(i + 3) * M_ROWS + r];
        }
        float s = (p0 + p1) + (p2 + p3);
        out[r] = g_cm[r] + logf(s) - QBIAS * LN2F - g_logW;
    }
}

// ---------------------------------------------------------------------------
extern "C" void kernel_launch(void* const* d_in, const int* in_sizes, int n_in,
                              void* d_out, int out_size) {
    const float* testX  = (const float*)d_in[0];
    const float* trainX = (const float*)d_in[1];
    const float* w      = (const float*)d_in[2];
    float* out = (float*)d_out;

    static int smem_set = 0;
    if (!smem_set) {
        cudaFuncSetAttribute(kde_main, cudaFuncAttributeMaxDynamicSharedMemorySize, SMEM_BYTES);
        smem_set = 1;
    }

    // 384 conversion blocks + 1 fused wsum block
    kde_pre<<<((M_ROWS + N_ROWS) * 4) / 256 + 1, 256>>>(testX, trainX, w);
    kde_main<<<M_ROWS / MT * NSLICES, 256, SMEM_BYTES>>>();
    kde_final<<<(M_ROWS + 127) / 128, 128>>>(out);
}